// round 6
// baseline (speedup 1.0000x reference)
#include <cuda_runtime.h>
#include <cuda_bf16.h>
#include <math.h>
#include <stdint.h>

#define BB 2
#define LL 2048
#define DD 1024
#define HH 16
#define DKK 64
#define DFF 4096
#define MM (BB*LL)   // 4096
#define EPS 1e-5f

// ================= helpers =================
__device__ __forceinline__ uint32_t smem_u32(const void* p) {
    uint32_t a;
    asm("{ .reg .u64 t; cvta.to.shared.u64 t, %1; cvt.u32.u64 %0, t; }" : "=r"(a) : "l"(p));
    return a;
}

#define LDSM_X4(r, addr) \
    asm volatile("ldmatrix.sync.aligned.m8n8.x4.shared.b16 {%0,%1,%2,%3}, [%4];" \
        : "=r"((r)[0]), "=r"((r)[1]), "=r"((r)[2]), "=r"((r)[3]) : "r"(addr))
#define LDSM_X4T(r, addr) \
    asm volatile("ldmatrix.sync.aligned.m8n8.x4.trans.shared.b16 {%0,%1,%2,%3}, [%4];" \
        : "=r"((r)[0]), "=r"((r)[1]), "=r"((r)[2]), "=r"((r)[3]) : "r"(addr))

#define MMA16816(d, a, b0, b1) \
    asm volatile("mma.sync.aligned.m16n8k16.row.col.f32.bf16.bf16.f32 " \
        "{%0,%1,%2,%3}, {%4,%5,%6,%7}, {%8,%9}, {%0,%1,%2,%3};" \
        : "+f"((d)[0]), "+f"((d)[1]), "+f"((d)[2]), "+f"((d)[3]) \
        : "r"((a)[0]), "r"((a)[1]), "r"((a)[2]), "r"((a)[3]), "r"(b0), "r"(b1))

#define STS64U(addr, a, b) \
    asm volatile("st.shared.v2.b32 [%0], {%1, %2};" \
                 :: "r"((uint32_t)(addr)), "r"(a), "r"(b) : "memory")

__device__ __forceinline__ void cpa16(uint32_t dst, const void* src) {
    asm volatile("cp.async.cg.shared.global [%0], [%1], 16;" :: "r"(dst), "l"(src));
}
#define CP_COMMIT() asm volatile("cp.async.commit_group;" ::: "memory")
#define CP_WAIT2()  asm volatile("cp.async.wait_group 2;" ::: "memory")

// exact split: x = hi + lo, hi = truncate-to-bf16(x); pack pairs (x0 -> low half)
__device__ __forceinline__ void split2(float x0, float x1, uint32_t& hi, uint32_t& lo) {
    uint32_t u0 = __float_as_uint(x0) & 0xffff0000u;
    uint32_t u1 = __float_as_uint(x1) & 0xffff0000u;
    hi = (u0 >> 16) | u1;
    float l0 = x0 - __uint_as_float(u0);
    float l1 = x1 - __uint_as_float(u1);
    __nv_bfloat162 p = __float22bfloat162_rn(make_float2(l0, l1));
    lo = *reinterpret_cast<uint32_t*>(&p);
}
__device__ __forceinline__ uint32_t packbf(float x0, float x1) {
    __nv_bfloat162 p = __float22bfloat162_rn(make_float2(x0, x1));
    return *reinterpret_cast<uint32_t*>(&p);
}

// ================= scratch =================
__device__ float g_q   [BB*LL*DD];
__device__ float g_k   [BB*LL*DD];
__device__ float g_v   [BB*LL*DD];
__device__ float g_vsuf[BB*HH*LL*DKK];
__device__ float g_y1  [BB*LL*DD];
__device__ float g_part[BB*256*2];
__device__ float g_stats[BB*2];

// bf16 hi/lo split operands
__device__ __nv_bfloat16 g_xh  [BB*LL*DD],  g_xl  [BB*LL*DD];
__device__ __nv_bfloat16 g_lnyh[BB*LL*DD],  g_lnyl[BB*LL*DD];
__device__ __nv_bfloat16 g_ln1h[BB*LL*DD],  g_ln1l[BB*LL*DD];
__device__ __nv_bfloat16 g_ath [BB*LL*DD],  g_atl [BB*LL*DD];
__device__ __nv_bfloat16 g_hh  [BB*LL*DFF], g_hl  [BB*LL*DFF];
__device__ __nv_bfloat16 g_wqh[DD*DD],  g_wql[DD*DD];
__device__ __nv_bfloat16 g_wkh[DD*DD],  g_wkl[DD*DD];
__device__ __nv_bfloat16 g_wvh[DD*DD],  g_wvl[DD*DD];
__device__ __nv_bfloat16 g_woh[DD*DD],  g_wol[DD*DD];
__device__ __nv_bfloat16 g_w1h[DD*DFF], g_w1l[DD*DFF];
__device__ __nv_bfloat16 g_w2h[DFF*DD], g_w2l[DFF*DD];

// ================= fp32 -> bf16 hi/lo split =================
__global__ void convert_split(const float4* __restrict__ src,
                              uint2* __restrict__ hi, uint2* __restrict__ lo, int n4) {
    int i = blockIdx.x * blockDim.x + threadIdx.x;
    if (i < n4) {
        float4 v = src[i];
        uint32_t h0,l0,h1,l1;
        split2(v.x, v.y, h0, l0);
        split2(v.z, v.w, h1, l1);
        hi[i] = make_uint2(h0, h1);
        lo[i] = make_uint2(l0, l1);
    }
}

// ================= LayerNorm over (L,D) jointly =================
__global__ void ln_reduce1(const float* __restrict__ x) {
    const int batch = blockIdx.y;
    const int chunk = (LL*DD)/256;
    long base = (long)batch*LL*DD + (long)blockIdx.x*chunk;
    float s = 0.f, s2 = 0.f;
    for (int i = threadIdx.x; i < chunk; i += 256) {
        float v = x[base + i];
        s += v; s2 += v*v;
    }
    __shared__ float sh[256], sh2[256];
    sh[threadIdx.x] = s; sh2[threadIdx.x] = s2;
    __syncthreads();
    for (int o = 128; o > 0; o >>= 1) {
        if (threadIdx.x < o) { sh[threadIdx.x] += sh[threadIdx.x+o]; sh2[threadIdx.x] += sh2[threadIdx.x+o]; }
        __syncthreads();
    }
    if (threadIdx.x == 0) {
        g_part[(batch*256 + blockIdx.x)*2 + 0] = sh[0];
        g_part[(batch*256 + blockIdx.x)*2 + 1] = sh2[0];
    }
}

__global__ void ln_reduce2() {
    const int batch = blockIdx.x;
    __shared__ float sh[256], sh2[256];
    sh[threadIdx.x]  = g_part[(batch*256 + threadIdx.x)*2 + 0];
    sh2[threadIdx.x] = g_part[(batch*256 + threadIdx.x)*2 + 1];
    __syncthreads();
    for (int o = 128; o > 0; o >>= 1) {
        if (threadIdx.x < o) { sh[threadIdx.x] += sh[threadIdx.x+o]; sh2[threadIdx.x] += sh2[threadIdx.x+o]; }
        __syncthreads();
    }
    if (threadIdx.x == 0) {
        const float inv = 1.0f / (float)(LL*DD);
        float mu  = sh[0]  * inv;
        float var = sh2[0] * inv - mu*mu;
        g_stats[batch*2 + 0] = mu;
        g_stats[batch*2 + 1] = rsqrtf(var + EPS);
    }
}

// LN apply writing bf16 hi/lo split directly
__global__ void ln_apply_split(const float* __restrict__ x, const float* __restrict__ w,
                               const float* __restrict__ b,
                               __nv_bfloat16* __restrict__ ohi, __nv_bfloat16* __restrict__ olo) {
    const int batch = blockIdx.y;
    const float mu   = g_stats[batch*2 + 0];
    const float rstd = g_stats[batch*2 + 1];
    const long base = (long)batch*LL*DD;
    const int n4 = LL*DD/4;
    for (int i = blockIdx.x*blockDim.x + threadIdx.x; i < n4; i += gridDim.x*blockDim.x) {
        const long idx = (long)i*4;
        float4 xv = *(const float4*)(x + base + idx);
        float4 wv = *(const float4*)(w + idx);
        float4 bv = *(const float4*)(b + idx);
        float4 v;
        v.x = (xv.x - mu)*rstd*wv.x + bv.x;
        v.y = (xv.y - mu)*rstd*wv.y + bv.y;
        v.z = (xv.z - mu)*rstd*wv.z + bv.z;
        v.w = (xv.w - mu)*rstd*wv.w + bv.w;
        uint32_t h0,l0,h1,l1;
        split2(v.x, v.y, h0, l0);
        split2(v.z, v.w, h1, l1);
        *(uint2*)(ohi + base + idx) = make_uint2(h0, h1);
        *(uint2*)(olo + base + idx) = make_uint2(l0, l1);
    }
}

// ================= pipelined bf16x3 GEMM =================
// CTA 128x256, warp tile 64x64, k-chunk 32, 4-buffer cp.async pipeline.
// Inputs pre-split bf16 hi/lo. EPI: 0=bias, 1=bias+relu, 2=bias+residual.
// OUTM: 0 = fp32 C, 1 = bf16 hi/lo split (Chi/Clo).
#define ASTR2 80
#define BSTR2 528
#define OFF_ALO2 10240
#define OFF_BHI2 20480
#define OFF_BLO2 37376
#define STAGE2   54272
#define SMEM_GEMM (4*STAGE2)

template<int EPI, int OUTM>
__global__ void __launch_bounds__(256, 1)
tgemm(const __nv_bfloat16* __restrict__ Ahi, const __nv_bfloat16* __restrict__ Alo,
      const __nv_bfloat16* __restrict__ Whi, const __nv_bfloat16* __restrict__ Wlo,
      const float* __restrict__ bias, const float* __restrict__ R,
      float* __restrict__ C, __nv_bfloat16* __restrict__ Chi, __nv_bfloat16* __restrict__ Clo,
      int N, int K)
{
    extern __shared__ __align__(128) char sm[];
    const uint32_t sbase = smem_u32(sm);

    const int t = threadIdx.x;
    const int lane = t & 31, wid = t >> 5;
    const int g = lane >> 2, tig = lane & 3;
    const int wm = wid >> 2, wn = wid & 3;        // 2 x 4 warp grid
    const int bm = blockIdx.y * 128, bn = blockIdx.x * 256;

    // cp.async source pointers / smem offsets
    const __nv_bfloat16* AgHi = Ahi + (size_t)(bm + (t>>1))*K + (t&1)*16;
    const __nv_bfloat16* AgLo = Alo + (size_t)(bm + (t>>1))*K + (t&1)*16;
    const __nv_bfloat16* BgHi = Whi + (size_t)(t>>3)*N + bn + (t&7)*32;
    const __nv_bfloat16* BgLo = Wlo + (size_t)(t>>3)*N + bn + (t&7)*32;
    const uint32_t a_sts = (uint32_t)(t>>1)*ASTR2 + (uint32_t)(t&1)*32;
    const uint32_t b_sts = (uint32_t)(t>>3)*BSTR2 + (uint32_t)(t&7)*64;

    // ldmatrix bases
    const uint32_t a_base = sbase + (uint32_t)(wm*64 + (lane & 15)) * ASTR2 + ((lane >> 4) & 1) * 16;
    const uint32_t b_base = sbase + OFF_BHI2 + (uint32_t)(lane & 15) * BSTR2 + (uint32_t)wn * 128 + ((lane >> 4) & 1) * 16;

    float acc[4][8][4];
    #pragma unroll
    for (int i = 0; i < 4; i++)
        #pragma unroll
        for (int j = 0; j < 8; j++)
            #pragma unroll
            for (int c = 0; c < 4; c++) acc[i][j][c] = 0.f;

    const int nk = K / 32;

    auto issue = [&](int s, int buf) {
        const int k0 = s * 32;
        const uint32_t sb = sbase + (uint32_t)buf * STAGE2;
        const __nv_bfloat16* ah_ = AgHi + k0;
        const __nv_bfloat16* al_ = AgLo + k0;
        cpa16(sb + a_sts,                 ah_);
        cpa16(sb + a_sts + 16,            ah_ + 8);
        cpa16(sb + OFF_ALO2 + a_sts,      al_);
        cpa16(sb + OFF_ALO2 + a_sts + 16, al_ + 8);
        const __nv_bfloat16* bh_ = BgHi + (size_t)k0 * N;
        const __nv_bfloat16* bl_ = BgLo + (size_t)k0 * N;
        cpa16(sb + OFF_BHI2 + b_sts,      bh_);
        cpa16(sb + OFF_BHI2 + b_sts + 16, bh_ + 8);
        cpa16(sb + OFF_BHI2 + b_sts + 32, bh_ + 16);
        cpa16(sb + OFF_BHI2 + b_sts + 48, bh_ + 24);
        cpa16(sb + OFF_BLO2 + b_sts,      bl_);
        cpa16(sb + OFF_BLO2 + b_sts + 16, bl_ + 8);
        cpa16(sb + OFF_BLO2 + b_sts + 32, bl_ + 16);
        cpa16(sb + OFF_BLO2 + b_sts + 48, bl_ + 24);
    };

    issue(0, 0); CP_COMMIT();
    if (nk > 1) issue(1, 1);
    CP_COMMIT();

    for (int s = 0; s < nk; s++) {
        if (s + 2 < nk) issue(s + 2, (s + 2) & 3);
        CP_COMMIT();
        CP_WAIT2();
        __syncthreads();

        const uint32_t so = (uint32_t)(s & 3) * STAGE2;
        #pragma unroll
        for (int ks = 0; ks < 2; ks++) {
            uint32_t ah[4][4], bh[8][2];
            #pragma unroll
            for (int i = 0; i < 4; i++)
                LDSM_X4(ah[i], a_base + so + ks*32 + i*(16*ASTR2));
            #pragma unroll
            for (int j2 = 0; j2 < 4; j2++) {
                uint32_t tmp[4];
                LDSM_X4T(tmp, b_base + so + ks*(16*BSTR2) + j2*32);
                bh[2*j2][0] = tmp[0]; bh[2*j2][1] = tmp[1];
                bh[2*j2+1][0] = tmp[2]; bh[2*j2+1][1] = tmp[3];
            }
            // pass 1: A-hi x B-hi
            #pragma unroll
            for (int i = 0; i < 4; i++)
                #pragma unroll
                for (int j = 0; j < 8; j++)
                    MMA16816(acc[i][j], ah[i], bh[j][0], bh[j][1]);
            // pass 2: A-lo x B-hi
            {
                uint32_t al[4][4];
                #pragma unroll
                for (int i = 0; i < 4; i++)
                    LDSM_X4(al[i], a_base + so + OFF_ALO2 + ks*32 + i*(16*ASTR2));
                #pragma unroll
                for (int i = 0; i < 4; i++)
                    #pragma unroll
                    for (int j = 0; j < 8; j++)
                        MMA16816(acc[i][j], al[i], bh[j][0], bh[j][1]);
            }
            // pass 3: A-hi x B-lo
            #pragma unroll
            for (int j2 = 0; j2 < 4; j2++) {
                uint32_t tmp[4];
                LDSM_X4T(tmp, b_base + so + (OFF_BLO2 - OFF_BHI2) + ks*(16*BSTR2) + j2*32);
                bh[2*j2][0] = tmp[0]; bh[2*j2][1] = tmp[1];
                bh[2*j2+1][0] = tmp[2]; bh[2*j2+1][1] = tmp[3];
            }
            #pragma unroll
            for (int i = 0; i < 4; i++)
                #pragma unroll
                for (int j = 0; j < 8; j++)
                    MMA16816(acc[i][j], ah[i], bh[j][0], bh[j][1]);
        }
    }

    // epilogue
    #pragma unroll
    for (int i = 0; i < 4; i++) {
        const int row0 = bm + wm*64 + i*16 + g;
        #pragma unroll
        for (int j = 0; j < 8; j++) {
            const int col0 = bn + wn*64 + j*8 + 2*tig;
            float2 bs = *(const float2*)(bias + col0);
            float2 c01 = make_float2(acc[i][j][0] + bs.x, acc[i][j][1] + bs.y);
            float2 c23 = make_float2(acc[i][j][2] + bs.x, acc[i][j][3] + bs.y);
            if (EPI == 1) {
                c01.x = fmaxf(c01.x, 0.f); c01.y = fmaxf(c01.y, 0.f);
                c23.x = fmaxf(c23.x, 0.f); c23.y = fmaxf(c23.y, 0.f);
            }
            if (EPI == 2) {
                float2 r0 = *(const float2*)(R + (size_t)row0 * N + col0);
                float2 r1 = *(const float2*)(R + (size_t)(row0+8) * N + col0);
                c01.x += r0.x; c01.y += r0.y;
                c23.x += r1.x; c23.y += r1.y;
            }
            if (OUTM == 0) {
                *(float2*)(C + (size_t)row0 * N + col0)     = c01;
                *(float2*)(C + (size_t)(row0+8) * N + col0) = c23;
            } else {
                uint32_t hh, ll;
                split2(c01.x, c01.y, hh, ll);
                *(uint32_t*)(Chi + (size_t)row0 * N + col0) = hh;
                *(uint32_t*)(Clo + (size_t)row0 * N + col0) = ll;
                split2(c23.x, c23.y, hh, ll);
                *(uint32_t*)(Chi + (size_t)(row0+8) * N + col0) = hh;
                *(uint32_t*)(Clo + (size_t)(row0+8) * N + col0) = ll;
            }
        }
    }
}

// ================= V suffix sums (segmented scan) =================
__global__ void __launch_bounds__(1024) vsuffix_kernel() {
    const int bh = blockIdx.x;
    const int b = bh / HH, h = bh % HH;
    const int d = threadIdx.x & 63;
    const int seg = threadIdx.x >> 6;
    const int SEGK = LL / 16;
    __shared__ float part[16][64];
    const size_t vbase = (size_t)b*LL*DD + (size_t)h*DKK + d;
    const int k0 = seg * SEGK;
    float s = 0.f;
    for (int k = k0; k < k0 + SEGK; k++) s += g_v[vbase + (size_t)k*DD];
    part[seg][d] = s;
    __syncthreads();
    float acc = 0.f;
    for (int ss = seg + 1; ss < 16; ss++) acc += part[ss][d];
    const size_t sb = (size_t)bh*LL*DKK + d;
    for (int k = k0 + SEGK - 1; k >= k0; k--) {
        g_vsuf[sb + (size_t)k*DKK] = acc;
        acc += g_v[vbase + (size_t)k*DD];
    }
}

// ================= tensor-core flash attention (writes bf16 split) =================
#define TSTR 144
#define QTILE 9216

__global__ void __launch_bounds__(128)
fattn_kernel() {
    __shared__ __align__(16) char smr[5*QTILE];
    const uint32_t sQhi = smem_u32(smr);
    const uint32_t sQlo = sQhi + QTILE;
    const uint32_t sKhi = sQhi + 2*QTILE;
    const uint32_t sKlo = sQhi + 3*QTILE;
    const uint32_t sV   = sQhi + 4*QTILE;

    const int b = blockIdx.z, h = blockIdx.y;
    const int qt = gridDim.x - 1 - blockIdx.x;   // heavy tiles first
    const int q0 = qt * 64;
    const int t = threadIdx.x, w = t >> 5, lane = t & 31;
    const int g = lane >> 2, tg = lane & 3;

    const float SC = 0.125f * 1.4426950408889634f;

    {
        const int r = t >> 1, hf = t & 1;
        const float* qp = g_q + ((size_t)(b*LL + q0 + r))*DD + h*DKK + hf*32;
        const uint32_t dhi = sQhi + (uint32_t)r*TSTR + hf*64;
        const uint32_t dlo = sQlo + (uint32_t)r*TSTR + hf*64;
        #pragma unroll
        for (int j = 0; j < 8; j++) {
            float4 v = *(const float4*)(qp + j*4);
            v.x *= SC; v.y *= SC; v.z *= SC; v.w *= SC;
            uint32_t h0,l0,h1,l1;
            split2(v.x, v.y, h0, l0); split2(v.z, v.w, h1, l1);
            STS64U(dhi + j*8, h0, h1);
            STS64U(dlo + j*8, l0, l1);
        }
    }
    __syncthreads();

    uint32_t qh[4][4], qlo[4][4];
    {
        const int mi = lane >> 3, li = lane & 7;
        const uint32_t ro = (uint32_t)(w*16 + ((mi&1)<<3) + li) * TSTR + (uint32_t)((mi>>1)<<4);
        #pragma unroll
        for (int kc4 = 0; kc4 < 4; kc4++) {
            LDSM_X4(qh[kc4],  sQhi + ro + kc4*32);
            LDSM_X4(qlo[kc4], sQlo + ro + kc4*32);
        }
    }

    float oacc[8][4];
    #pragma unroll
    for (int f = 0; f < 8; f++)
        #pragma unroll
        for (int c = 0; c < 4; c++) oacc[f][c] = 0.f;
    float ls0 = 0.f, ls1 = 0.f;

    const int nch = qt + 1;
    const int mi = lane >> 3, li = lane & 7;

    for (int ci = 0; ci < nch; ci++) {
        const int kc = ci * 64;
        __syncthreads();
        {
            const int r = t >> 1, hf = t & 1;
            const size_t gbase = ((size_t)(b*LL + kc + r))*DD + h*DKK + hf*32;
            const float* kp = g_k + gbase;
            const float* vp = g_v + gbase;
            const uint32_t dkh = sKhi + (uint32_t)r*TSTR + hf*64;
            const uint32_t dkl = sKlo + (uint32_t)r*TSTR + hf*64;
            const uint32_t dv  = sV   + (uint32_t)r*TSTR + hf*64;
            #pragma unroll
            for (int j = 0; j < 8; j++) {
                float4 kv = *(const float4*)(kp + j*4);
                uint32_t h0,l0,h1,l1;
                split2(kv.x, kv.y, h0, l0); split2(kv.z, kv.w, h1, l1);
                STS64U(dkh + j*8, h0, h1);
                STS64U(dkl + j*8, l0, l1);
                float4 vv = *(const float4*)(vp + j*4);
                STS64U(dv + j*8, packbf(vv.x, vv.y), packbf(vv.z, vv.w));
            }
        }
        __syncthreads();

        float sacc[8][4];
        #pragma unroll
        for (int f = 0; f < 8; f++)
            #pragma unroll
            for (int c = 0; c < 4; c++) sacc[f][c] = 0.f;

        #pragma unroll
        for (int kc4 = 0; kc4 < 4; kc4++) {
            uint32_t bk[8][2];
            #pragma unroll
            for (int j2 = 0; j2 < 4; j2++) {
                uint32_t tmp[4];
                const uint32_t ro = (uint32_t)((2*j2 + (mi>>1))*8 + li) * TSTR
                                  + (uint32_t)(kc4*32 + (mi&1)*16);
                LDSM_X4(tmp, sKhi + ro);
                bk[2*j2][0] = tmp[0]; bk[2*j2][1] = tmp[1];
                bk[2*j2+1][0] = tmp[2]; bk[2*j2+1][1] = tmp[3];
            }
            #pragma unroll
            for (int f = 0; f < 8; f++) MMA16816(sacc[f], qh[kc4], bk[f][0], bk[f][1]);
            #pragma unroll
            for (int f = 0; f < 8; f++) MMA16816(sacc[f], qlo[kc4], bk[f][0], bk[f][1]);
            #pragma unroll
            for (int j2 = 0; j2 < 4; j2++) {
                uint32_t tmp[4];
                const uint32_t ro = (uint32_t)((2*j2 + (mi>>1))*8 + li) * TSTR
                                  + (uint32_t)(kc4*32 + (mi&1)*16);
                LDSM_X4(tmp, sKlo + ro);
                bk[2*j2][0] = tmp[0]; bk[2*j2][1] = tmp[1];
                bk[2*j2+1][0] = tmp[2]; bk[2*j2+1][1] = tmp[3];
            }
            #pragma unroll
            for (int f = 0; f < 8; f++) MMA16816(sacc[f], qh[kc4], bk[f][0], bk[f][1]);
        }

        const int row0 = q0 + w*16 + g;
        if (ci == nch - 1) {
            #pragma unroll
            for (int f = 0; f < 8; f++) {
                const int col = kc + f*8 + 2*tg;
                sacc[f][0] = (col   <= row0)   ? exp2f(sacc[f][0]) : 0.f;
                sacc[f][1] = (col+1 <= row0)   ? exp2f(sacc[f][1]) : 0.f;
                sacc[f][2] = (col   <= row0+8) ? exp2f(sacc[f][2]) : 0.f;
                sacc[f][3] = (col+1 <= row0+8) ? exp2f(sacc[f][3]) : 0.f;
            }
        } else {
            #pragma unroll
            for (int f = 0; f < 8; f++) {
                sacc[f][0] = exp2f(sacc[f][0]);
                sacc[f][1] = exp2f(sacc[f][1]);
                sacc[f][2] = exp2f(sacc[f][2]);
                sacc[f][3] = exp2f(sacc[f][3]);
            }
        }
        #pragma unroll
        for (int f = 0; f < 8; f++) {
            ls0 += sacc[f][0] + sacc[f][1];
            ls1 += sacc[f][2] + sacc[f][3];
        }

        #pragma unroll
        for (int kc4 = 0; kc4 < 4; kc4++) {
            uint32_t aP[4];
            aP[0] = packbf(sacc[2*kc4][0],   sacc[2*kc4][1]);
            aP[1] = packbf(sacc[2*kc4][2],   sacc[2*kc4][3]);
            aP[2] = packbf(sacc[2*kc4+1][0], sacc[2*kc4+1][1]);
            aP[3] = packbf(sacc[2*kc4+1][2], sacc[2*kc4+1][3]);
            uint32_t bv[8][2];
            #pragma unroll
            for (int j2 = 0; j2 < 4; j2++) {
                uint32_t tmp[4];
                const uint32_t ro = (uint32_t)(kc4*16 + (mi&1)*8 + li) * TSTR
                                  + (uint32_t)((2*j2 + (mi>>1))*16);
                LDSM_X4T(tmp, sV + ro);
                bv[2*j2][0] = tmp[0]; bv[2*j2][1] = tmp[1];
                bv[2*j2+1][0] = tmp[2]; bv[2*j2+1][1] = tmp[3];
            }
            #pragma unroll
            for (int f = 0; f < 8; f++) MMA16816(oacc[f], aP, bv[f][0], bv[f][1]);
        }
    }

    ls0 += __shfl_xor_sync(0xffffffffu, ls0, 1);
    ls0 += __shfl_xor_sync(0xffffffffu, ls0, 2);
    ls1 += __shfl_xor_sync(0xffffffffu, ls1, 1);
    ls1 += __shfl_xor_sync(0xffffffffu, ls1, 2);

    const int row0 = q0 + w*16 + g;
    const int row1 = row0 + 8;
    const float inv0 = 1.0f / (ls0 + (float)(LL - 1 - row0));
    const float inv1 = 1.0f / (ls1 + (float)(LL - 1 - row1));

    const size_t vs0 = ((size_t)((b*HH + h)*LL) + row0) * DKK;
    const size_t vs1 = ((size_t)((b*HH + h)*LL) + row1) * DKK;
    const size_t ob0 = ((size_t)(b*LL + row0))*DD + h*DKK;
    const size_t ob1 = ((size_t)(b*LL + row1))*DD + h*DKK;
    #pragma unroll
    for (int f = 0; f < 8; f++) {
        const int col = f*8 + 2*tg;
        float2 t0 = *(const float2*)(g_vsuf + vs0 + col);
        float2 t1 = *(const float2*)(g_vsuf + vs1 + col);
        uint32_t hh, ll;
        split2((oacc[f][0] + t0.x) * inv0, (oacc[f][1] + t0.y) * inv0, hh, ll);
        *(uint32_t*)(g_ath + ob0 + col) = hh;
        *(uint32_t*)(g_atl + ob0 + col) = ll;
        split2((oacc[f][2] + t1.x) * inv1, (oacc[f][3] + t1.y) * inv1, hh, ll);
        *(uint32_t*)(g_ath + ob1 + col) = hh;
        *(uint32_t*)(g_atl + ob1 + col) = ll;
    }
}

// ================= launch =================
static void conv(const float* src, __nv_bfloat16* hi, __nv_bfloat16* lo, int n) {
    int n4 = n / 4;
    convert_split<<<(n4 + 255)/256, 256>>>((const float4*)src, (uint2*)hi, (uint2*)lo, n4);
}

extern "C" void kernel_launch(void* const* d_in, const int* in_sizes, int n_in,
                              void* d_out, int out_size) {
    const float* x    = (const float*)d_in[0];
    const float* y    = (const float*)d_in[1];
    const float* Wq   = (const float*)d_in[2];
    const float* bq   = (const float*)d_in[3];
    const float* Wk   = (const float*)d_in[4];
    const float* bk   = (const float*)d_in[5];
    const float* Wv   = (const float*)d_in[6];
    const float* bv   = (const float*)d_in[7];
    const float* Wo   = (const float*)d_in[8];
    const float* bo   = (const float*)d_in[9];
    const float* W1   = (const float*)d_in[10];
    const float* b1   = (const float*)d_in[11];
    const float* W2   = (const float*)d_in[12];
    const float* b2   = (const float*)d_in[13];
    const float* ln1w = (const float*)d_in[14];
    const float* ln1b = (const float*)d_in[15];
    const float* ln2w = (const float*)d_in[16];
    const float* ln2b = (const float*)d_in[17];
    float* out = (float*)d_out;

    float *p_q, *p_k, *p_v, *p_y1;
    cudaGetSymbolAddress((void**)&p_q,  g_q);
    cudaGetSymbolAddress((void**)&p_k,  g_k);
    cudaGetSymbolAddress((void**)&p_v,  g_v);
    cudaGetSymbolAddress((void**)&p_y1, g_y1);

    __nv_bfloat16 *xh,*xl,*lnyh,*lnyl,*ln1h,*ln1l,*ath,*atl,*hh,*hl;
    __nv_bfloat16 *wqh,*wql,*wkh,*wkl,*wvh,*wvl,*woh,*wol,*w1h,*w1l,*w2h,*w2l;
    cudaGetSymbolAddress((void**)&xh, g_xh);   cudaGetSymbolAddress((void**)&xl, g_xl);
    cudaGetSymbolAddress((void**)&lnyh, g_lnyh); cudaGetSymbolAddress((void**)&lnyl, g_lnyl);
    cudaGetSymbolAddress((void**)&ln1h, g_ln1h); cudaGetSymbolAddress((void**)&ln1l, g_ln1l);
    cudaGetSymbolAddress((void**)&ath, g_ath); cudaGetSymbolAddress((void**)&atl, g_atl);
    cudaGetSymbolAddress((void**)&hh, g_hh);   cudaGetSymbolAddress((void**)&hl, g_hl);
    cudaGetSymbolAddress((void**)&wqh, g_wqh); cudaGetSymbolAddress((void**)&wql, g_wql);
    cudaGetSymbolAddress((void**)&wkh, g_wkh); cudaGetSymbolAddress((void**)&wkl, g_wkl);
    cudaGetSymbolAddress((void**)&wvh, g_wvh); cudaGetSymbolAddress((void**)&wvl, g_wvl);
    cudaGetSymbolAddress((void**)&woh, g_woh); cudaGetSymbolAddress((void**)&wol, g_wol);
    cudaGetSymbolAddress((void**)&w1h, g_w1h); cudaGetSymbolAddress((void**)&w1l, g_w1l);
    cudaGetSymbolAddress((void**)&w2h, g_w2h); cudaGetSymbolAddress((void**)&w2l, g_w2l);

    cudaFuncSetAttribute(tgemm<0,0>, cudaFuncAttributeMaxDynamicSharedMemorySize, SMEM_GEMM);
    cudaFuncSetAttribute(tgemm<2,0>, cudaFuncAttributeMaxDynamicSharedMemorySize, SMEM_GEMM);
    cudaFuncSetAttribute(tgemm<1,1>, cudaFuncAttributeMaxDynamicSharedMemorySize, SMEM_GEMM);

    // operand conversions (independent of LN)
    conv(x,  xh,  xl,  BB*LL*DD);
    conv(Wq, wqh, wql, DD*DD);
    conv(Wk, wkh, wkl, DD*DD);
    conv(Wv, wvh, wvl, DD*DD);
    conv(Wo, woh, wol, DD*DD);
    conv(W1, w1h, w1l, DD*DFF);
    conv(W2, w2h, w2l, DFF*DD);

    // LN1 on y -> split lny
    ln_reduce1<<<dim3(256, BB), 256>>>(y);
    ln_reduce2<<<BB, 256>>>();
    ln_apply_split<<<dim3(128, BB), 256>>>(y, ln1w, ln1b, lnyh, lnyl);

    // Q = x@Wq+bq ; K = lny@Wk+bk ; V = lny@Wv+bv  (fp32 outputs)
    tgemm<0,0><<<dim3(DD/256, MM/128), 256, SMEM_GEMM>>>(xh, xl, wqh, wql, bq, nullptr, p_q, nullptr, nullptr, DD, DD);
    tgemm<0,0><<<dim3(DD/256, MM/128), 256, SMEM_GEMM>>>(lnyh, lnyl, wkh, wkl, bk, nullptr, p_k, nullptr, nullptr, DD, DD);
    tgemm<0,0><<<dim3(DD/256, MM/128), 256, SMEM_GEMM>>>(lnyh, lnyl, wvh, wvl, bv, nullptr, p_v, nullptr, nullptr, DD, DD);

    // suffix sums of V, then attention (writes attn split)
    vsuffix_kernel<<<BB*HH, 1024>>>();
    fattn_kernel<<<dim3(LL/64, HH, BB), 128>>>();

    // y1 = y + attn@Wo + bo  (fp32)
    tgemm<2,0><<<dim3(DD/256, MM/128), 256, SMEM_GEMM>>>(ath, atl, woh, wol, bo, y, p_y1, nullptr, nullptr, DD, DD);

    // LN2 on y1 -> split lny1
    ln_reduce1<<<dim3(256, BB), 256>>>(p_y1);
    ln_reduce2<<<BB, 256>>>();
    ln_apply_split<<<dim3(128, BB), 256>>>(p_y1, ln2w, ln2b, ln1h, ln1l);

    // h = relu(lny1@W1 + b1)  (bf16 split out) ; out = y1 + h@W2 + b2 (fp32)
    tgemm<1,1><<<dim3(DFF/256, MM/128), 256, SMEM_GEMM>>>(ln1h, ln1l, w1h, w1l, b1, nullptr, nullptr, hh, hl, DFF, DD);
    tgemm<2,0><<<dim3(DD/256,  MM/128), 256, SMEM_GEMM>>>(hh, hl, w2h, w2l, b2, p_y1, out, nullptr, nullptr, DD, DFF);
}

// round 8
// speedup vs baseline: 1.3097x; 1.3097x over previous
#include <cuda_runtime.h>
#include <cuda_bf16.h>
#include <cuda_fp16.h>
#include <math.h>
#include <stdint.h>

#define BB 2
#define LL 2048
#define DD 1024
#define HH 16
#define DKK 64
#define DFF 4096
#define MM (BB*LL)   // 4096
#define EPS 1e-5f

// ================= helpers =================
__device__ __forceinline__ uint32_t smem_u32(const void* p) {
    uint32_t a;
    asm("{ .reg .u64 t; cvta.to.shared.u64 t, %1; cvt.u32.u64 %0, t; }" : "=r"(a) : "l"(p));
    return a;
}

#define LDSM_X4(r, addr) \
    asm volatile("ldmatrix.sync.aligned.m8n8.x4.shared.b16 {%0,%1,%2,%3}, [%4];" \
        : "=r"((r)[0]), "=r"((r)[1]), "=r"((r)[2]), "=r"((r)[3]) : "r"(addr))
#define LDSM_X4T(r, addr) \
    asm volatile("ldmatrix.sync.aligned.m8n8.x4.trans.shared.b16 {%0,%1,%2,%3}, [%4];" \
        : "=r"((r)[0]), "=r"((r)[1]), "=r"((r)[2]), "=r"((r)[3]) : "r"(addr))

// bf16 mma (attention)
#define MMA16816(d, a, b0, b1) \
    asm volatile("mma.sync.aligned.m16n8k16.row.col.f32.bf16.bf16.f32 " \
        "{%0,%1,%2,%3}, {%4,%5,%6,%7}, {%8,%9}, {%0,%1,%2,%3};" \
        : "+f"((d)[0]), "+f"((d)[1]), "+f"((d)[2]), "+f"((d)[3]) \
        : "r"((a)[0]), "r"((a)[1]), "r"((a)[2]), "r"((a)[3]), "r"(b0), "r"(b1))

// fp16 mma (GEMM)
#define MMAH16816(d, a, b0, b1) \
    asm volatile("mma.sync.aligned.m16n8k16.row.col.f32.f16.f16.f32 " \
        "{%0,%1,%2,%3}, {%4,%5,%6,%7}, {%8,%9}, {%0,%1,%2,%3};" \
        : "+f"((d)[0]), "+f"((d)[1]), "+f"((d)[2]), "+f"((d)[3]) \
        : "r"((a)[0]), "r"((a)[1]), "r"((a)[2]), "r"((a)[3]), "r"(b0), "r"(b1))

#define STS128U(addr, a, b, c, d) \
    asm volatile("st.shared.v4.b32 [%0], {%1, %2, %3, %4};" \
                 :: "r"((uint32_t)(addr)), "r"(a), "r"(b), "r"(c), "r"(d) : "memory")
#define STS64U(addr, a, b) \
    asm volatile("st.shared.v2.b32 [%0], {%1, %2};" \
                 :: "r"((uint32_t)(addr)), "r"(a), "r"(b) : "memory")

// bf16 exact split (attention QK path)
__device__ __forceinline__ void split2(float x0, float x1, uint32_t& hi, uint32_t& lo) {
    uint32_t u0 = __float_as_uint(x0) & 0xffff0000u;
    uint32_t u1 = __float_as_uint(x1) & 0xffff0000u;
    hi = (u0 >> 16) | u1;
    float l0 = x0 - __uint_as_float(u0);
    float l1 = x1 - __uint_as_float(u1);
    __nv_bfloat162 p = __float22bfloat162_rn(make_float2(l0, l1));
    lo = *reinterpret_cast<uint32_t*>(&p);
}
__device__ __forceinline__ uint32_t packbf(float x0, float x1) {
    __nv_bfloat162 p = __float22bfloat162_rn(make_float2(x0, x1));
    return *reinterpret_cast<uint32_t*>(&p);
}
// fp16: A split (residual rounded, err ~2^-22), B single round
__device__ __forceinline__ void split2h(float x0, float x1, uint32_t& hi, uint32_t& lo) {
    __half2 h = __floats2half2_rn(x0, x1);
    float l0 = x0 - __half2float(__low2half(h));
    float l1 = x1 - __half2float(__high2half(h));
    __half2 l = __floats2half2_rn(l0, l1);
    hi = *reinterpret_cast<uint32_t*>(&h);
    lo = *reinterpret_cast<uint32_t*>(&l);
}
__device__ __forceinline__ uint32_t packh(float x0, float x1) {
    __half2 h = __floats2half2_rn(x0, x1);
    return *reinterpret_cast<uint32_t*>(&h);
}

// ================= scratch =================
__device__ float g_lny [BB*LL*DD];
__device__ float g_q   [BB*LL*DD];
__device__ float g_k   [BB*LL*DD];
__device__ float g_v   [BB*LL*DD];
__device__ float g_vsuf[BB*HH*LL*DKK];
__device__ float g_attn[BB*LL*DD];
__device__ float g_y1  [BB*LL*DD];
__device__ float g_lny1[BB*LL*DD];
__device__ float g_h   [BB*LL*DFF];
__device__ float g_part[BB*256*2];
__device__ float g_stats[BB*2];

// ================= LayerNorm over (L,D) jointly =================
__global__ void ln_reduce1(const float* __restrict__ x) {
    const int batch = blockIdx.y;
    const int chunk = (LL*DD)/256;
    long base = (long)batch*LL*DD + (long)blockIdx.x*chunk;
    float s = 0.f, s2 = 0.f;
    for (int i = threadIdx.x; i < chunk; i += 256) {
        float v = x[base + i];
        s += v; s2 += v*v;
    }
    __shared__ float sh[256], sh2[256];
    sh[threadIdx.x] = s; sh2[threadIdx.x] = s2;
    __syncthreads();
    for (int o = 128; o > 0; o >>= 1) {
        if (threadIdx.x < o) { sh[threadIdx.x] += sh[threadIdx.x+o]; sh2[threadIdx.x] += sh2[threadIdx.x+o]; }
        __syncthreads();
    }
    if (threadIdx.x == 0) {
        g_part[(batch*256 + blockIdx.x)*2 + 0] = sh[0];
        g_part[(batch*256 + blockIdx.x)*2 + 1] = sh2[0];
    }
}

__global__ void ln_reduce2() {
    const int batch = blockIdx.x;
    __shared__ float sh[256], sh2[256];
    sh[threadIdx.x]  = g_part[(batch*256 + threadIdx.x)*2 + 0];
    sh2[threadIdx.x] = g_part[(batch*256 + threadIdx.x)*2 + 1];
    __syncthreads();
    for (int o = 128; o > 0; o >>= 1) {
        if (threadIdx.x < o) { sh[threadIdx.x] += sh[threadIdx.x+o]; sh2[threadIdx.x] += sh2[threadIdx.x+o]; }
        __syncthreads();
    }
    if (threadIdx.x == 0) {
        const float inv = 1.0f / (float)(LL*DD);
        float mu  = sh[0]  * inv;
        float var = sh2[0] * inv - mu*mu;
        g_stats[batch*2 + 0] = mu;
        g_stats[batch*2 + 1] = rsqrtf(var + EPS);
    }
}

__global__ void ln_apply(const float* __restrict__ x, const float* __restrict__ w,
                         const float* __restrict__ b, float* __restrict__ out) {
    const int batch = blockIdx.y;
    const float mu   = g_stats[batch*2 + 0];
    const float rstd = g_stats[batch*2 + 1];
    const long base = (long)batch*LL*DD;
    for (long i = (long)blockIdx.x*blockDim.x + threadIdx.x; i < (long)LL*DD; i += (long)gridDim.x*blockDim.x) {
        out[base + i] = (x[base + i] - mu) * rstd * w[i] + b[i];
    }
}

// ================= fp16 2-pass mma.sync GEMM =================
// C[M,N] = A[M,K]@W[K,N] + bias (+relu / +residual)
// A exact-split fp16 (hi+lo, 2 passes); B single fp16 (rounding err ~2^-11.8).
// CTA 256 thr, tile 128x128, k-chunk 16, double buffered.
#define ASTR 48
#define BSTR 272
#define OFF_ALO 6144
#define OFF_B   12288
#define STAGE   16640

template<int EPI>
__global__ void __launch_bounds__(256)
tgemm(const float* __restrict__ A, const float* __restrict__ W,
      const float* __restrict__ bias, const float* __restrict__ R,
      float* __restrict__ C, int N, int K)
{
    __shared__ __align__(128) char sm[2*STAGE];
    const uint32_t sbase = smem_u32(sm);

    const int t = threadIdx.x;
    const int lane = t & 31, wid = t >> 5;
    const int g = lane >> 2, tig = lane & 3;
    const int wm = wid >> 2, wn = wid & 3;         // 2 x 4 warp grid, warp tile 64x32
    const int bm = blockIdx.y * 128, bn = blockIdx.x * 128;

    const int ar = t >> 1, aq = t & 1;             // A: row, k-half
    const int br = t >> 4, bc = (t & 15) * 8;      // B: k row, n col base

    const float* Agp = A + (size_t)(bm + ar) * K + aq * 8;
    const float* Bgp = W + (size_t)br * N + bn + bc;

    const uint32_t a_base = sbase + (uint32_t)(wm*64 + (lane & 15)) * ASTR + ((lane >> 4) & 1) * 16;
    const uint32_t b_base = sbase + OFF_B + (uint32_t)(lane & 15) * BSTR + (uint32_t)wn * 64 + ((lane >> 4) & 1) * 16;

    float acc[4][4][4];
    #pragma unroll
    for (int i = 0; i < 4; i++)
        #pragma unroll
        for (int j = 0; j < 4; j++)
            #pragma unroll
            for (int c = 0; c < 4; c++) acc[i][j][c] = 0.f;

    const int nk = K / 16;

    float4 av0, av1, bv0, bv1;
    av0 = *(const float4*)(Agp);
    av1 = *(const float4*)(Agp + 4);
    bv0 = *(const float4*)(Bgp);
    bv1 = *(const float4*)(Bgp + 4);

    auto store_stage = [&](int buf) {
        const uint32_t sb = sbase + (uint32_t)buf * STAGE;
        uint32_t h0,l0,h1,l1,h2,l2,h3,l3;
        // A: fp16 split
        split2h(av0.x, av0.y, h0, l0);
        split2h(av0.z, av0.w, h1, l1);
        split2h(av1.x, av1.y, h2, l2);
        split2h(av1.z, av1.w, h3, l3);
        uint32_t aaddr = sb + (uint32_t)ar * ASTR + (uint32_t)aq * 16;
        STS128U(aaddr, h0, h1, h2, h3);
        STS128U(aaddr + OFF_ALO, l0, l1, l2, l3);
        // B: single fp16
        uint32_t baddr = sb + OFF_B + (uint32_t)br * BSTR + (uint32_t)bc * 2;
        STS128U(baddr, packh(bv0.x, bv0.y), packh(bv0.z, bv0.w),
                        packh(bv1.x, bv1.y), packh(bv1.z, bv1.w));
    };

    store_stage(0);
    __syncthreads();

    for (int s = 0; s < nk; s++) {
        const int buf = s & 1;
        if (s + 1 < nk) {
            const int k0 = (s + 1) * 16;
            av0 = *(const float4*)(Agp + k0);
            av1 = *(const float4*)(Agp + k0 + 4);
            bv0 = *(const float4*)(Bgp + (size_t)k0 * N);
            bv1 = *(const float4*)(Bgp + (size_t)k0 * N + 4);
        }

        const uint32_t so = (uint32_t)buf * STAGE;
        uint32_t ah[4][4], bf[2][4];
        #pragma unroll
        for (int i = 0; i < 4; i++) LDSM_X4(ah[i], a_base + so + i * (16*ASTR));
        #pragma unroll
        for (int j2 = 0; j2 < 2; j2++) LDSM_X4T(bf[j2], b_base + so + j2 * 32);

        // pass 1: A-hi x B
        #pragma unroll
        for (int i = 0; i < 4; i++)
            #pragma unroll
            for (int j = 0; j < 4; j++)
                MMAH16816(acc[i][j], ah[i], bf[j>>1][(j&1)*2], bf[j>>1][(j&1)*2+1]);

        // pass 2: A-lo x B
        {
            uint32_t al[4][4];
            #pragma unroll
            for (int i = 0; i < 4; i++) LDSM_X4(al[i], a_base + so + OFF_ALO + i * (16*ASTR));
            #pragma unroll
            for (int i = 0; i < 4; i++)
                #pragma unroll
                for (int j = 0; j < 4; j++)
                    MMAH16816(acc[i][j], al[i], bf[j>>1][(j&1)*2], bf[j>>1][(j&1)*2+1]);
        }

        if (s + 1 < nk) store_stage(buf ^ 1);
        __syncthreads();
    }

    // epilogue
    #pragma unroll
    for (int i = 0; i < 4; i++) {
        const int row0 = bm + wm*64 + i*16 + g;
        #pragma unroll
        for (int j = 0; j < 4; j++) {
            const int col0 = bn + wn*32 + j*8 + 2*tig;
            float2 bs = *(const float2*)(bias + col0);
            float2 c01 = make_float2(acc[i][j][0] + bs.x, acc[i][j][1] + bs.y);
            float2 c23 = make_float2(acc[i][j][2] + bs.x, acc[i][j][3] + bs.y);
            if (EPI == 1) {
                c01.x = fmaxf(c01.x, 0.f); c01.y = fmaxf(c01.y, 0.f);
                c23.x = fmaxf(c23.x, 0.f); c23.y = fmaxf(c23.y, 0.f);
            }
            if (EPI == 2) {
                float2 r0 = *(const float2*)(R + (size_t)row0 * N + col0);
                float2 r1 = *(const float2*)(R + (size_t)(row0+8) * N + col0);
                c01.x += r0.x; c01.y += r0.y;
                c23.x += r1.x; c23.y += r1.y;
            }
            *(float2*)(C + (size_t)row0 * N + col0)     = c01;
            *(float2*)(C + (size_t)(row0+8) * N + col0) = c23;
        }
    }
}

// ================= V suffix sums (segmented scan) =================
__global__ void __launch_bounds__(1024) vsuffix_kernel() {
    const int bh = blockIdx.x;
    const int b = bh / HH, h = bh % HH;
    const int d = threadIdx.x & 63;
    const int seg = threadIdx.x >> 6;
    const int SEGK = LL / 16;
    __shared__ float part[16][64];
    const size_t vbase = (size_t)b*LL*DD + (size_t)h*DKK + d;
    const int k0 = seg * SEGK;
    float s = 0.f;
    for (int k = k0; k < k0 + SEGK; k++) s += g_v[vbase + (size_t)k*DD];
    part[seg][d] = s;
    __syncthreads();
    float acc = 0.f;
    for (int ss = seg + 1; ss < 16; ss++) acc += part[ss][d];
    const size_t sb = (size_t)bh*LL*DKK + d;
    for (int k = k0 + SEGK - 1; k >= k0; k--) {
        g_vsuf[sb + (size_t)k*DKK] = acc;
        acc += g_v[vbase + (size_t)k*DD];
    }
}

// ================= tensor-core flash attention (bf16, unchanged from R4) =================
#define TSTR 144
#define QTILE 9216

__global__ void __launch_bounds__(128)
fattn_kernel(float* __restrict__ out) {
    __shared__ __align__(16) char smr[5*QTILE];
    const uint32_t sQhi = smem_u32(smr);
    const uint32_t sQlo = sQhi + QTILE;
    const uint32_t sKhi = sQhi + 2*QTILE;
    const uint32_t sKlo = sQhi + 3*QTILE;
    const uint32_t sV   = sQhi + 4*QTILE;

    const int b = blockIdx.z, h = blockIdx.y;
    const int qt = gridDim.x - 1 - blockIdx.x;   // heavy tiles first
    const int q0 = qt * 64;
    const int t = threadIdx.x, w = t >> 5, lane = t & 31;
    const int g = lane >> 2, tg = lane & 3;

    const float SC = 0.125f * 1.4426950408889634f;

    {
        const int r = t >> 1, hf = t & 1;
        const float* qp = g_q + ((size_t)(b*LL + q0 + r))*DD + h*DKK + hf*32;
        const uint32_t dhi = sQhi + (uint32_t)r*TSTR + hf*64;
        const uint32_t dlo = sQlo + (uint32_t)r*TSTR + hf*64;
        #pragma unroll
        for (int j = 0; j < 8; j++) {
            float4 v = *(const float4*)(qp + j*4);
            v.x *= SC; v.y *= SC; v.z *= SC; v.w *= SC;
            uint32_t h0,l0,h1,l1;
            split2(v.x, v.y, h0, l0); split2(v.z, v.w, h1, l1);
            STS64U(dhi + j*8, h0, h1);
            STS64U(dlo + j*8, l0, l1);
        }
    }
    __syncthreads();

    uint32_t qh[4][4], qlo[4][4];
    {
        const int mi = lane >> 3, li = lane & 7;
        const uint32_t ro = (uint32_t)(w*16 + ((mi&1)<<3) + li) * TSTR + (uint32_t)((mi>>1)<<4);
        #pragma unroll
        for (int kc4 = 0; kc4 < 4; kc4++) {
            LDSM_X4(qh[kc4],  sQhi + ro + kc4*32);
            LDSM_X4(qlo[kc4], sQlo + ro + kc4*32);
        }
    }

    float oacc[8][4];
    #pragma unroll
    for (int f = 0; f < 8; f++)
        #pragma unroll
        for (int c = 0; c < 4; c++) oacc[f][c] = 0.f;
    float ls0 = 0.f, ls1 = 0.f;

    const int nch = qt + 1;
    const int mi = lane >> 3, li = lane & 7;

    for (int ci = 0; ci < nch; ci++) {
        const int kc = ci * 64;
        __syncthreads();
        {
            const int r = t >> 1, hf = t & 1;
            const size_t gbase = ((size_t)(b*LL + kc + r))*DD + h*DKK + hf*32;
            const float* kp = g_k + gbase;
            const float* vp = g_v + gbase;
            const uint32_t dkh = sKhi + (uint32_t)r*TSTR + hf*64;
            const uint32_t dkl = sKlo + (uint32_t)r*TSTR + hf*64;
            const uint32_t dv  = sV   + (uint32_t)r*TSTR + hf*64;
            #pragma unroll
            for (int j = 0; j < 8; j++) {
                float4 kv = *(const float4*)(kp + j*4);
                uint32_t h0,l0,h1,l1;
                split2(kv.x, kv.y, h0, l0); split2(kv.z, kv.w, h1, l1);
                STS64U(dkh + j*8, h0, h1);
                STS64U(dkl + j*8, l0, l1);
                float4 vv = *(const float4*)(vp + j*4);
                STS64U(dv + j*8, packbf(vv.x, vv.y), packbf(vv.z, vv.w));
            }
        }
        __syncthreads();

        float sacc[8][4];
        #pragma unroll
        for (int f = 0; f < 8; f++)
            #pragma unroll
            for (int c = 0; c < 4; c++) sacc[f][c] = 0.f;

        #pragma unroll
        for (int kc4 = 0; kc4 < 4; kc4++) {
            uint32_t bk[8][2];
            #pragma unroll
            for (int j2 = 0; j2 < 4; j2++) {
                uint32_t tmp[4];
                const uint32_t ro = (uint32_t)((2*j2 + (mi>>1))*8 + li) * TSTR
                                  + (uint32_t)(kc4*32 + (mi&1)*16);
                LDSM_X4(tmp, sKhi + ro);
                bk[2*j2][0] = tmp[0]; bk[2*j2][1] = tmp[1];
                bk[2*j2+1][0] = tmp[2]; bk[2*j2+1][1] = tmp[3];
            }
            #pragma unroll
            for (int f = 0; f < 8; f++) MMA16816(sacc[f], qh[kc4], bk[f][0], bk[f][1]);
            #pragma unroll
            for (int f = 0; f < 8; f++) MMA16816(sacc[f], qlo[kc4], bk[f][0], bk[f][1]);
            #pragma unroll
            for (int j2 = 0; j2 < 4; j2++) {
                uint32_t tmp[4];
                const uint32_t ro = (uint32_t)((2*j2 + (mi>>1))*8 + li) * TSTR
                                  + (uint32_t)(kc4*32 + (mi&1)*16);
                LDSM_X4(tmp, sKlo + ro);
                bk[2*j2][0] = tmp[0]; bk[2*j2][1] = tmp[1];
                bk[2*j2+1][0] = tmp[2]; bk[2*j2+1][1] = tmp[3];
            }
            #pragma unroll
            for (int f = 0; f < 8; f++) MMA16816(sacc[f], qh[kc4], bk[f][0], bk[f][1]);
        }

        const int row0 = q0 + w*16 + g;
        if (ci == nch - 1) {
            #pragma unroll
            for (int f = 0; f < 8; f++) {
                const int col = kc + f*8 + 2*tg;
                sacc[f][0] = (col   <= row0)   ? exp2f(sacc[f][0]) : 0.f;
                sacc[f][1] = (col+1 <= row0)   ? exp2f(sacc[f][1]) : 0.f;
                sacc[f][2] = (col   <= row0+8) ? exp2f(sacc[f][2]) : 0.f;
                sacc[f][3] = (col+1 <= row0+8) ? exp2f(sacc[f][3]) : 0.f;
            }
        } else {
            #pragma unroll
            for (int f = 0; f < 8; f++) {
                sacc[f][0] = exp2f(sacc[f][0]);
                sacc[f][1] = exp2f(sacc[f][1]);
                sacc[f][2] = exp2f(sacc[f][2]);
                sacc[f][3] = exp2f(sacc[f][3]);
            }
        }
        #pragma unroll
        for (int f = 0; f < 8; f++) {
            ls0 += sacc[f][0] + sacc[f][1];
            ls1 += sacc[f][2] + sacc[f][3];
        }

        #pragma unroll
        for (int kc4 = 0; kc4 < 4; kc4++) {
            uint32_t aP[4];
            aP[0] = packbf(sacc[2*kc4][0],   sacc[2*kc4][1]);
            aP[1] = packbf(sacc[2*kc4][2],   sacc[2*kc4][3]);
            aP[2] = packbf(sacc[2*kc4+1][0], sacc[2*kc4+1][1]);
            aP[3] = packbf(sacc[2*kc4+1][2], sacc[2*kc4+1][3]);
            uint32_t bv[8][2];
            #pragma unroll
            for (int j2 = 0; j2 < 4; j2++) {
                uint32_t tmp[4];
                const uint32_t ro = (uint32_t)(kc4*16 + (mi&1)*8 + li) * TSTR
                                  + (uint32_t)((2*j2 + (mi>>1))*16);
                LDSM_X4T(tmp, sV + ro);
                bv[2*j2][0] = tmp[0]; bv[2*j2][1] = tmp[1];
                bv[2*j2+1][0] = tmp[2]; bv[2*j2+1][1] = tmp[3];
            }
            #pragma unroll
            for (int f = 0; f < 8; f++) MMA16816(oacc[f], aP, bv[f][0], bv[f][1]);
        }
    }

    ls0 += __shfl_xor_sync(0xffffffffu, ls0, 1);
    ls0 += __shfl_xor_sync(0xffffffffu, ls0, 2);
    ls1 += __shfl_xor_sync(0xffffffffu, ls1, 1);
    ls1 += __shfl_xor_sync(0xffffffffu, ls1, 2);

    const int row0 = q0 + w*16 + g;
    const int row1 = row0 + 8;
    const float inv0 = 1.0f / (ls0 + (float)(LL - 1 - row0));
    const float inv1 = 1.0f / (ls1 + (float)(LL - 1 - row1));

    const size_t vs0 = ((size_t)((b*HH + h)*LL) + row0) * DKK;
    const size_t vs1 = ((size_t)((b*HH + h)*LL) + row1) * DKK;
    float* o0 = out + ((size_t)(b*LL + row0))*DD + h*DKK;
    float* o1 = out + ((size_t)(b*LL + row1))*DD + h*DKK;
    #pragma unroll
    for (int f = 0; f < 8; f++) {
        const int col = f*8 + 2*tg;
        float2 t0 = *(const float2*)(g_vsuf + vs0 + col);
        float2 t1 = *(const float2*)(g_vsuf + vs1 + col);
        float2 r0 = make_float2((oacc[f][0] + t0.x) * inv0, (oacc[f][1] + t0.y) * inv0);
        float2 r1 = make_float2((oacc[f][2] + t1.x) * inv1, (oacc[f][3] + t1.y) * inv1);
        *(float2*)(o0 + col) = r0;
        *(float2*)(o1 + col) = r1;
    }
}

// ================= launch =================
extern "C" void kernel_launch(void* const* d_in, const int* in_sizes, int n_in,
                              void* d_out, int out_size) {
    const float* x    = (const float*)d_in[0];
    const float* y    = (const float*)d_in[1];
    const float* Wq   = (const float*)d_in[2];
    const float* bq   = (const float*)d_in[3];
    const float* Wk   = (const float*)d_in[4];
    const float* bk   = (const float*)d_in[5];
    const float* Wv   = (const float*)d_in[6];
    const float* bv   = (const float*)d_in[7];
    const float* Wo   = (const float*)d_in[8];
    const float* bo   = (const float*)d_in[9];
    const float* W1   = (const float*)d_in[10];
    const float* b1   = (const float*)d_in[11];
    const float* W2   = (const float*)d_in[12];
    const float* b2   = (const float*)d_in[13];
    const float* ln1w = (const float*)d_in[14];
    const float* ln1b = (const float*)d_in[15];
    const float* ln2w = (const float*)d_in[16];
    const float* ln2b = (const float*)d_in[17];
    float* out = (float*)d_out;

    float *p_lny, *p_q, *p_k, *p_v, *p_attn, *p_y1, *p_lny1, *p_h;
    cudaGetSymbolAddress((void**)&p_lny,  g_lny);
    cudaGetSymbolAddress((void**)&p_q,    g_q);
    cudaGetSymbolAddress((void**)&p_k,    g_k);
    cudaGetSymbolAddress((void**)&p_v,    g_v);
    cudaGetSymbolAddress((void**)&p_attn, g_attn);
    cudaGetSymbolAddress((void**)&p_y1,   g_y1);
    cudaGetSymbolAddress((void**)&p_lny1, g_lny1);
    cudaGetSymbolAddress((void**)&p_h,    g_h);

    // LN1 on y
    ln_reduce1<<<dim3(256, BB), 256>>>(y);
    ln_reduce2<<<BB, 256>>>();
    ln_apply<<<dim3(256, BB), 256>>>(y, ln1w, ln1b, p_lny);

    // Q = x@Wq+bq ; K = lny@Wk+bk ; V = lny@Wv+bv
    tgemm<0><<<dim3(DD/128, MM/128), 256>>>(x,     Wq, bq, nullptr, p_q, DD, DD);
    tgemm<0><<<dim3(DD/128, MM/128), 256>>>(p_lny, Wk, bk, nullptr, p_k, DD, DD);
    tgemm<0><<<dim3(DD/128, MM/128), 256>>>(p_lny, Wv, bv, nullptr, p_v, DD, DD);

    // suffix sums of V, then attention
    vsuffix_kernel<<<BB*HH, 1024>>>();
    fattn_kernel<<<dim3(LL/64, HH, BB), 128>>>(p_attn);

    // y1 = y + attn@Wo + bo
    tgemm<2><<<dim3(DD/128, MM/128), 256>>>(p_attn, Wo, bo, y, p_y1, DD, DD);

    // LN2 on y1
    ln_reduce1<<<dim3(256, BB), 256>>>(p_y1);
    ln_reduce2<<<BB, 256>>>();
    ln_apply<<<dim3(256, BB), 256>>>(p_y1, ln2w, ln2b, p_lny1);

    // h = relu(lny1@W1 + b1) ; out = y1 + h@W2 + b2
    tgemm<1><<<dim3(DFF/128, MM/128), 256>>>(p_lny1, W1, b1, nullptr, p_h, DFF, DD);
    tgemm<2><<<dim3(DD/128,  MM/128), 256>>>(p_h,    W2, b2, p_y1,    out, DD, DFF);
}

// round 9
// speedup vs baseline: 1.8050x; 1.3782x over previous
#include <cuda_runtime.h>
#include <cuda_bf16.h>
#include <cuda_fp16.h>
#include <math.h>
#include <stdint.h>

#define BB 2
#define LL 2048
#define DD 1024
#define HH 16
#define DKK 64
#define DFF 4096
#define MM (BB*LL)   // 4096
#define EPS 1e-5f

// ================= helpers =================
__device__ __forceinline__ uint32_t smem_u32(const void* p) {
    uint32_t a;
    asm("{ .reg .u64 t; cvta.to.shared.u64 t, %1; cvt.u32.u64 %0, t; }" : "=r"(a) : "l"(p));
    return a;
}

#define LDSM_X4(r, addr) \
    asm volatile("ldmatrix.sync.aligned.m8n8.x4.shared.b16 {%0,%1,%2,%3}, [%4];" \
        : "=r"((r)[0]), "=r"((r)[1]), "=r"((r)[2]), "=r"((r)[3]) : "r"(addr))
#define LDSM_X4T(r, addr) \
    asm volatile("ldmatrix.sync.aligned.m8n8.x4.trans.shared.b16 {%0,%1,%2,%3}, [%4];" \
        : "=r"((r)[0]), "=r"((r)[1]), "=r"((r)[2]), "=r"((r)[3]) : "r"(addr))

// bf16 mma (attention)
#define MMA16816(d, a, b0, b1) \
    asm volatile("mma.sync.aligned.m16n8k16.row.col.f32.bf16.bf16.f32 " \
        "{%0,%1,%2,%3}, {%4,%5,%6,%7}, {%8,%9}, {%0,%1,%2,%3};" \
        : "+f"((d)[0]), "+f"((d)[1]), "+f"((d)[2]), "+f"((d)[3]) \
        : "r"((a)[0]), "r"((a)[1]), "r"((a)[2]), "r"((a)[3]), "r"(b0), "r"(b1))

// fp16 mma (GEMM)
#define MMAH16816(d, a, b0, b1) \
    asm volatile("mma.sync.aligned.m16n8k16.row.col.f32.f16.f16.f32 " \
        "{%0,%1,%2,%3}, {%4,%5,%6,%7}, {%8,%9}, {%0,%1,%2,%3};" \
        : "+f"((d)[0]), "+f"((d)[1]), "+f"((d)[2]), "+f"((d)[3]) \
        : "r"((a)[0]), "r"((a)[1]), "r"((a)[2]), "r"((a)[3]), "r"(b0), "r"(b1))

#define STS128U(addr, a, b, c, d) \
    asm volatile("st.shared.v4.b32 [%0], {%1, %2, %3, %4};" \
                 :: "r"((uint32_t)(addr)), "r"(a), "r"(b), "r"(c), "r"(d) : "memory")
#define STS64U(addr, a, b) \
    asm volatile("st.shared.v2.b32 [%0], {%1, %2};" \
                 :: "r"((uint32_t)(addr)), "r"(a), "r"(b) : "memory")

// bf16 exact split (attention QK path)
__device__ __forceinline__ void split2(float x0, float x1, uint32_t& hi, uint32_t& lo) {
    uint32_t u0 = __float_as_uint(x0) & 0xffff0000u;
    uint32_t u1 = __float_as_uint(x1) & 0xffff0000u;
    hi = (u0 >> 16) | u1;
    float l0 = x0 - __uint_as_float(u0);
    float l1 = x1 - __uint_as_float(u1);
    __nv_bfloat162 p = __float22bfloat162_rn(make_float2(l0, l1));
    lo = *reinterpret_cast<uint32_t*>(&p);
}
__device__ __forceinline__ uint32_t packbf(float x0, float x1) {
    __nv_bfloat162 p = __float22bfloat162_rn(make_float2(x0, x1));
    return *reinterpret_cast<uint32_t*>(&p);
}
__device__ __forceinline__ uint32_t packh(float x0, float x1) {
    __half2 h = __floats2half2_rn(x0, x1);
    return *reinterpret_cast<uint32_t*>(&h);
}

// ================= scratch =================
__device__ float g_q   [BB*LL*DD];
__device__ float g_k   [BB*LL*DD];
__device__ float g_v   [BB*LL*DD];
__device__ float g_vsuf[BB*HH*LL*DKK];
__device__ float g_y1  [BB*LL*DD];
__device__ float g_part[BB*256*2];
__device__ float g_stats[BB*2];

// fp16 operands
__device__ __half g_xh  [BB*LL*DD];
__device__ __half g_lnyh[BB*LL*DD];
__device__ __half g_ln1h[BB*LL*DD];
__device__ __half g_atth[BB*LL*DD];
__device__ __half g_hh  [BB*LL*DFF];
__device__ __half g_wqh[DD*DD];
__device__ __half g_wkh[DD*DD];
__device__ __half g_wvh[DD*DD];
__device__ __half g_woh[DD*DD];
__device__ __half g_w1h[DD*DFF];
__device__ __half g_w2h[DFF*DD];

// ================= fp32 -> fp16 convert =================
__global__ void convert_h(const float4* __restrict__ src, uint2* __restrict__ dst, int n4) {
    int i = blockIdx.x * blockDim.x + threadIdx.x;
    if (i < n4) {
        float4 v = src[i];
        dst[i] = make_uint2(packh(v.x, v.y), packh(v.z, v.w));
    }
}

// ================= LayerNorm over (L,D) jointly =================
__global__ void ln_reduce1(const float* __restrict__ x) {
    const int batch = blockIdx.y;
    const int chunk = (LL*DD)/256;
    long base = (long)batch*LL*DD + (long)blockIdx.x*chunk;
    float s = 0.f, s2 = 0.f;
    for (int i = threadIdx.x; i < chunk; i += 256) {
        float v = x[base + i];
        s += v; s2 += v*v;
    }
    __shared__ float sh[256], sh2[256];
    sh[threadIdx.x] = s; sh2[threadIdx.x] = s2;
    __syncthreads();
    for (int o = 128; o > 0; o >>= 1) {
        if (threadIdx.x < o) { sh[threadIdx.x] += sh[threadIdx.x+o]; sh2[threadIdx.x] += sh2[threadIdx.x+o]; }
        __syncthreads();
    }
    if (threadIdx.x == 0) {
        g_part[(batch*256 + blockIdx.x)*2 + 0] = sh[0];
        g_part[(batch*256 + blockIdx.x)*2 + 1] = sh2[0];
    }
}

__global__ void ln_reduce2() {
    const int batch = blockIdx.x;
    __shared__ float sh[256], sh2[256];
    sh[threadIdx.x]  = g_part[(batch*256 + threadIdx.x)*2 + 0];
    sh2[threadIdx.x] = g_part[(batch*256 + threadIdx.x)*2 + 1];
    __syncthreads();
    for (int o = 128; o > 0; o >>= 1) {
        if (threadIdx.x < o) { sh[threadIdx.x] += sh[threadIdx.x+o]; sh2[threadIdx.x] += sh2[threadIdx.x+o]; }
        __syncthreads();
    }
    if (threadIdx.x == 0) {
        const float inv = 1.0f / (float)(LL*DD);
        float mu  = sh[0]  * inv;
        float var = sh2[0] * inv - mu*mu;
        g_stats[batch*2 + 0] = mu;
        g_stats[batch*2 + 1] = rsqrtf(var + EPS);
    }
}

// LN apply writing fp16 directly
__global__ void ln_apply_h(const float* __restrict__ x, const float* __restrict__ w,
                           const float* __restrict__ b, __half* __restrict__ out) {
    const int batch = blockIdx.y;
    const float mu   = g_stats[batch*2 + 0];
    const float rstd = g_stats[batch*2 + 1];
    const long base = (long)batch*LL*DD;
    const int n4 = LL*DD/4;
    for (int i = blockIdx.x*blockDim.x + threadIdx.x; i < n4; i += gridDim.x*blockDim.x) {
        const long idx = (long)i*4;
        float4 xv = *(const float4*)(x + base + idx);
        float4 wv = *(const float4*)(w + idx);
        float4 bv = *(const float4*)(b + idx);
        float v0 = (xv.x - mu)*rstd*wv.x + bv.x;
        float v1 = (xv.y - mu)*rstd*wv.y + bv.y;
        float v2 = (xv.z - mu)*rstd*wv.z + bv.z;
        float v3 = (xv.w - mu)*rstd*wv.w + bv.w;
        *(uint2*)(out + base + idx) = make_uint2(packh(v0, v1), packh(v2, v3));
    }
}

// ================= fp16 single-pass mma.sync GEMM =================
// C[M,N] = A[M,K]@W[K,N] + bias (+relu / +residual); A,W pre-converted fp16.
// CTA 256 thr, tile 128x128, k-chunk 32 (2 sub-tiles of 16), double buffered.
#define ASTR 48
#define OFF_A1 6144
#define OFF_B  12288
#define BSTR 272
#define BSUB 4352
#define STAGE 20992

template<int EPI, int OUTH>
__global__ void __launch_bounds__(256)
tgemm(const __half* __restrict__ A, const __half* __restrict__ W,
      const float* __restrict__ bias, const float* __restrict__ R,
      float* __restrict__ C, __half* __restrict__ Ch, int N, int K)
{
    __shared__ __align__(128) char sm[2*STAGE];
    const uint32_t sbase = smem_u32(sm);

    const int t = threadIdx.x;
    const int lane = t & 31, wid = t >> 5;
    const int g = lane >> 2, tig = lane & 3;
    const int wm = wid >> 2, wn = wid & 3;         // 2 x 4 warp grid, warp tile 64x32
    const int bm = blockIdx.y * 128, bn = blockIdx.x * 128;

    const int ar = t >> 1, aq = t & 1;             // A: row, k-eighth
    const int br = t >> 4, bc = (t & 15) * 8;      // B: k row, n col base

    const __half* Agp = A + (size_t)(bm + ar) * K + aq * 8;
    const __half* Bgp = W + (size_t)br * N + bn + bc;

    const uint32_t a_base = sbase + (uint32_t)(wm*64 + (lane & 15)) * ASTR + ((lane >> 4) & 1) * 16;
    const uint32_t b_base = sbase + OFF_B + (uint32_t)(lane & 15) * BSTR + (uint32_t)wn * 64 + ((lane >> 4) & 1) * 16;

    float acc[4][4][4];
    #pragma unroll
    for (int i = 0; i < 4; i++)
        #pragma unroll
        for (int j = 0; j < 4; j++)
            #pragma unroll
            for (int c = 0; c < 4; c++) acc[i][j][c] = 0.f;

    const int nk = K / 32;

    uint4 a0, a1, b0, b1;
    a0 = *(const uint4*)(Agp);
    a1 = *(const uint4*)(Agp + 16);
    b0 = *(const uint4*)(Bgp);
    b1 = *(const uint4*)(Bgp + (size_t)16 * N);

    auto store_stage = [&](int buf) {
        const uint32_t sb = sbase + (uint32_t)buf * STAGE;
        const uint32_t aaddr = sb + (uint32_t)ar * ASTR + (uint32_t)aq * 16;
        STS128U(aaddr,          a0.x, a0.y, a0.z, a0.w);
        STS128U(aaddr + OFF_A1, a1.x, a1.y, a1.z, a1.w);
        const uint32_t baddr = sb + OFF_B + (uint32_t)br * BSTR + (uint32_t)bc * 2;
        STS128U(baddr,        b0.x, b0.y, b0.z, b0.w);
        STS128U(baddr + BSUB, b1.x, b1.y, b1.z, b1.w);
    };

    store_stage(0);
    __syncthreads();

    for (int s = 0; s < nk; s++) {
        const int buf = s & 1;
        if (s + 1 < nk) {
            const int k0 = (s + 1) * 32;
            a0 = *(const uint4*)(Agp + k0);
            a1 = *(const uint4*)(Agp + k0 + 16);
            b0 = *(const uint4*)(Bgp + (size_t)k0 * N);
            b1 = *(const uint4*)(Bgp + (size_t)(k0 + 16) * N);
        }

        const uint32_t so = (uint32_t)buf * STAGE;
        #pragma unroll
        for (int ks = 0; ks < 2; ks++) {
            uint32_t ah[4][4], bf[2][4];
            #pragma unroll
            for (int i = 0; i < 4; i++)
                LDSM_X4(ah[i], a_base + so + ks*OFF_A1 + i*(16*ASTR));
            #pragma unroll
            for (int j2 = 0; j2 < 2; j2++)
                LDSM_X4T(bf[j2], b_base + so + ks*BSUB + j2*32);
            #pragma unroll
            for (int i = 0; i < 4; i++)
                #pragma unroll
                for (int j = 0; j < 4; j++)
                    MMAH16816(acc[i][j], ah[i], bf[j>>1][(j&1)*2], bf[j>>1][(j&1)*2+1]);
        }

        if (s + 1 < nk) store_stage(buf ^ 1);
        __syncthreads();
    }

    // epilogue
    #pragma unroll
    for (int i = 0; i < 4; i++) {
        const int row0 = bm + wm*64 + i*16 + g;
        #pragma unroll
        for (int j = 0; j < 4; j++) {
            const int col0 = bn + wn*32 + j*8 + 2*tig;
            float2 bs = *(const float2*)(bias + col0);
            float2 c01 = make_float2(acc[i][j][0] + bs.x, acc[i][j][1] + bs.y);
            float2 c23 = make_float2(acc[i][j][2] + bs.x, acc[i][j][3] + bs.y);
            if (EPI == 1) {
                c01.x = fmaxf(c01.x, 0.f); c01.y = fmaxf(c01.y, 0.f);
                c23.x = fmaxf(c23.x, 0.f); c23.y = fmaxf(c23.y, 0.f);
            }
            if (EPI == 2) {
                float2 r0 = *(const float2*)(R + (size_t)row0 * N + col0);
                float2 r1 = *(const float2*)(R + (size_t)(row0+8) * N + col0);
                c01.x += r0.x; c01.y += r0.y;
                c23.x += r1.x; c23.y += r1.y;
            }
            if (OUTH == 0) {
                *(float2*)(C + (size_t)row0 * N + col0)     = c01;
                *(float2*)(C + (size_t)(row0+8) * N + col0) = c23;
            } else {
                *(uint32_t*)(Ch + (size_t)row0 * N + col0)     = packh(c01.x, c01.y);
                *(uint32_t*)(Ch + (size_t)(row0+8) * N + col0) = packh(c23.x, c23.y);
            }
        }
    }
}

// ================= V suffix sums (segmented scan) =================
__global__ void __launch_bounds__(1024) vsuffix_kernel() {
    const int bh = blockIdx.x;
    const int b = bh / HH, h = bh % HH;
    const int d = threadIdx.x & 63;
    const int seg = threadIdx.x >> 6;
    const int SEGK = LL / 16;
    __shared__ float part[16][64];
    const size_t vbase = (size_t)b*LL*DD + (size_t)h*DKK + d;
    const int k0 = seg * SEGK;
    float s = 0.f;
    for (int k = k0; k < k0 + SEGK; k++) s += g_v[vbase + (size_t)k*DD];
    part[seg][d] = s;
    __syncthreads();
    float acc = 0.f;
    for (int ss = seg + 1; ss < 16; ss++) acc += part[ss][d];
    const size_t sb = (size_t)bh*LL*DKK + d;
    for (int k = k0 + SEGK - 1; k >= k0; k--) {
        g_vsuf[sb + (size_t)k*DKK] = acc;
        acc += g_v[vbase + (size_t)k*DD];
    }
}

// ================= tensor-core flash attention (bf16; writes fp16 attn) =================
#define TSTR 144
#define QTILE 9216

__global__ void __launch_bounds__(128)
fattn_kernel() {
    __shared__ __align__(16) char smr[5*QTILE];
    const uint32_t sQhi = smem_u32(smr);
    const uint32_t sQlo = sQhi + QTILE;
    const uint32_t sKhi = sQhi + 2*QTILE;
    const uint32_t sKlo = sQhi + 3*QTILE;
    const uint32_t sV   = sQhi + 4*QTILE;

    const int b = blockIdx.z, h = blockIdx.y;
    const int qt = gridDim.x - 1 - blockIdx.x;   // heavy tiles first
    const int q0 = qt * 64;
    const int t = threadIdx.x, w = t >> 5, lane = t & 31;
    const int g = lane >> 2, tg = lane & 3;

    const float SC = 0.125f * 1.4426950408889634f;

    {
        const int r = t >> 1, hf = t & 1;
        const float* qp = g_q + ((size_t)(b*LL + q0 + r))*DD + h*DKK + hf*32;
        const uint32_t dhi = sQhi + (uint32_t)r*TSTR + hf*64;
        const uint32_t dlo = sQlo + (uint32_t)r*TSTR + hf*64;
        #pragma unroll
        for (int j = 0; j < 8; j++) {
            float4 v = *(const float4*)(qp + j*4);
            v.x *= SC; v.y *= SC; v.z *= SC; v.w *= SC;
            uint32_t h0,l0,h1,l1;
            split2(v.x, v.y, h0, l0); split2(v.z, v.w, h1, l1);
            STS64U(dhi + j*8, h0, h1);
            STS64U(dlo + j*8, l0, l1);
        }
    }
    __syncthreads();

    uint32_t qh[4][4], qlo[4][4];
    {
        const int mi = lane >> 3, li = lane & 7;
        const uint32_t ro = (uint32_t)(w*16 + ((mi&1)<<3) + li) * TSTR + (uint32_t)((mi>>1)<<4);
        #pragma unroll
        for (int kc4 = 0; kc4 < 4; kc4++) {
            LDSM_X4(qh[kc4],  sQhi + ro + kc4*32);
            LDSM_X4(qlo[kc4], sQlo + ro + kc4*32);
        }
    }

    float oacc[8][4];
    #pragma unroll
    for (int f = 0; f < 8; f++)
        #pragma unroll
        for (int c = 0; c < 4; c++) oacc[f][c] = 0.f;
    float ls0 = 0.f, ls1 = 0.f;

    const int nch = qt + 1;
    const int mi = lane >> 3, li = lane & 7;

    for (int ci = 0; ci < nch; ci++) {
        const int kc = ci * 64;
        __syncthreads();
        {
            const int r = t >> 1, hf = t & 1;
            const size_t gbase = ((size_t)(b*LL + kc + r))*DD + h*DKK + hf*32;
            const float* kp = g_k + gbase;
            const float* vp = g_v + gbase;
            const uint32_t dkh = sKhi + (uint32_t)r*TSTR + hf*64;
            const uint32_t dkl = sKlo + (uint32_t)r*TSTR + hf*64;
            const uint32_t dv  = sV   + (uint32_t)r*TSTR + hf*64;
            #pragma unroll
            for (int j = 0; j < 8; j++) {
                float4 kv = *(const float4*)(kp + j*4);
                uint32_t h0,l0,h1,l1;
                split2(kv.x, kv.y, h0, l0); split2(kv.z, kv.w, h1, l1);
                STS64U(dkh + j*8, h0, h1);
                STS64U(dkl + j*8, l0, l1);
                float4 vv = *(const float4*)(vp + j*4);
                STS64U(dv + j*8, packbf(vv.x, vv.y), packbf(vv.z, vv.w));
            }
        }
        __syncthreads();

        float sacc[8][4];
        #pragma unroll
        for (int f = 0; f < 8; f++)
            #pragma unroll
            for (int c = 0; c < 4; c++) sacc[f][c] = 0.f;

        #pragma unroll
        for (int kc4 = 0; kc4 < 4; kc4++) {
            uint32_t bk[8][2];
            #pragma unroll
            for (int j2 = 0; j2 < 4; j2++) {
                uint32_t tmp[4];
                const uint32_t ro = (uint32_t)((2*j2 + (mi>>1))*8 + li) * TSTR
                                  + (uint32_t)(kc4*32 + (mi&1)*16);
                LDSM_X4(tmp, sKhi + ro);
                bk[2*j2][0] = tmp[0]; bk[2*j2][1] = tmp[1];
                bk[2*j2+1][0] = tmp[2]; bk[2*j2+1][1] = tmp[3];
            }
            #pragma unroll
            for (int f = 0; f < 8; f++) MMA16816(sacc[f], qh[kc4], bk[f][0], bk[f][1]);
            #pragma unroll
            for (int f = 0; f < 8; f++) MMA16816(sacc[f], qlo[kc4], bk[f][0], bk[f][1]);
            #pragma unroll
            for (int j2 = 0; j2 < 4; j2++) {
                uint32_t tmp[4];
                const uint32_t ro = (uint32_t)((2*j2 + (mi>>1))*8 + li) * TSTR
                                  + (uint32_t)(kc4*32 + (mi&1)*16);
                LDSM_X4(tmp, sKlo + ro);
                bk[2*j2][0] = tmp[0]; bk[2*j2][1] = tmp[1];
                bk[2*j2+1][0] = tmp[2]; bk[2*j2+1][1] = tmp[3];
            }
            #pragma unroll
            for (int f = 0; f < 8; f++) MMA16816(sacc[f], qh[kc4], bk[f][0], bk[f][1]);
        }

        const int row0 = q0 + w*16 + g;
        if (ci == nch - 1) {
            #pragma unroll
            for (int f = 0; f < 8; f++) {
                const int col = kc + f*8 + 2*tg;
                sacc[f][0] = (col   <= row0)   ? exp2f(sacc[f][0]) : 0.f;
                sacc[f][1] = (col+1 <= row0)   ? exp2f(sacc[f][1]) : 0.f;
                sacc[f][2] = (col   <= row0+8) ? exp2f(sacc[f][2]) : 0.f;
                sacc[f][3] = (col+1 <= row0+8) ? exp2f(sacc[f][3]) : 0.f;
            }
        } else {
            #pragma unroll
            for (int f = 0; f < 8; f++) {
                sacc[f][0] = exp2f(sacc[f][0]);
                sacc[f][1] = exp2f(sacc[f][1]);
                sacc[f][2] = exp2f(sacc[f][2]);
                sacc[f][3] = exp2f(sacc[f][3]);
            }
        }
        #pragma unroll
        for (int f = 0; f < 8; f++) {
            ls0 += sacc[f][0] + sacc[f][1];
            ls1 += sacc[f][2] + sacc[f][3];
        }

        #pragma unroll
        for (int kc4 = 0; kc4 < 4; kc4++) {
            uint32_t aP[4];
            aP[0] = packbf(sacc[2*kc4][0],   sacc[2*kc4][1]);
            aP[1] = packbf(sacc[2*kc4][2],   sacc[2*kc4][3]);
            aP[2] = packbf(sacc[2*kc4+1][0], sacc[2*kc4+1][1]);
            aP[3] = packbf(sacc[2*kc4+1][2], sacc[2*kc4+1][3]);
            uint32_t bv[8][2];
            #pragma unroll
            for (int j2 = 0; j2 < 4; j2++) {
                uint32_t tmp[4];
                const uint32_t ro = (uint32_t)(kc4*16 + (mi&1)*8 + li) * TSTR
                                  + (uint32_t)((2*j2 + (mi>>1))*16);
                LDSM_X4T(tmp, sV + ro);
                bv[2*j2][0] = tmp[0]; bv[2*j2][1] = tmp[1];
                bv[2*j2+1][0] = tmp[2]; bv[2*j2+1][1] = tmp[3];
            }
            #pragma unroll
            for (int f = 0; f < 8; f++) MMA16816(oacc[f], aP, bv[f][0], bv[f][1]);
        }
    }

    ls0 += __shfl_xor_sync(0xffffffffu, ls0, 1);
    ls0 += __shfl_xor_sync(0xffffffffu, ls0, 2);
    ls1 += __shfl_xor_sync(0xffffffffu, ls1, 1);
    ls1 += __shfl_xor_sync(0xffffffffu, ls1, 2);

    const int row0 = q0 + w*16 + g;
    const int row1 = row0 + 8;
    const float inv0 = 1.0f / (ls0 + (float)(LL - 1 - row0));
    const float inv1 = 1.0f / (ls1 + (float)(LL - 1 - row1));

    const size_t vs0 = ((size_t)((b*HH + h)*LL) + row0) * DKK;
    const size_t vs1 = ((size_t)((b*HH + h)*LL) + row1) * DKK;
    const size_t ob0 = ((size_t)(b*LL + row0))*DD + h*DKK;
    const size_t ob1 = ((size_t)(b*LL + row1))*DD + h*DKK;
    #pragma unroll
    for (int f = 0; f < 8; f++) {
        const int col = f*8 + 2*tg;
        float2 t0 = *(const float2*)(g_vsuf + vs0 + col);
        float2 t1 = *(const float2*)(g_vsuf + vs1 + col);
        *(uint32_t*)(g_atth + ob0 + col) = packh((oacc[f][0] + t0.x) * inv0, (oacc[f][1] + t0.y) * inv0);
        *(uint32_t*)(g_atth + ob1 + col) = packh((oacc[f][2] + t1.x) * inv1, (oacc[f][3] + t1.y) * inv1);
    }
}

// ================= launch =================
static void conv(const float* src, __half* dst, int n) {
    int n4 = n / 4;
    convert_h<<<(n4 + 255)/256, 256>>>((const float4*)src, (uint2*)dst, n4);
}

extern "C" void kernel_launch(void* const* d_in, const int* in_sizes, int n_in,
                              void* d_out, int out_size) {
    const float* x    = (const float*)d_in[0];
    const float* y    = (const float*)d_in[1];
    const float* Wq   = (const float*)d_in[2];
    const float* bq   = (const float*)d_in[3];
    const float* Wk   = (const float*)d_in[4];
    const float* bk   = (const float*)d_in[5];
    const float* Wv   = (const float*)d_in[6];
    const float* bv   = (const float*)d_in[7];
    const float* Wo   = (const float*)d_in[8];
    const float* bo   = (const float*)d_in[9];
    const float* W1   = (const float*)d_in[10];
    const float* b1   = (const float*)d_in[11];
    const float* W2   = (const float*)d_in[12];
    const float* b2   = (const float*)d_in[13];
    const float* ln1w = (const float*)d_in[14];
    const float* ln1b = (const float*)d_in[15];
    const float* ln2w = (const float*)d_in[16];
    const float* ln2b = (const float*)d_in[17];
    float* out = (float*)d_out;

    float *p_q, *p_k, *p_v, *p_y1;
    cudaGetSymbolAddress((void**)&p_q,  g_q);
    cudaGetSymbolAddress((void**)&p_k,  g_k);
    cudaGetSymbolAddress((void**)&p_v,  g_v);
    cudaGetSymbolAddress((void**)&p_y1, g_y1);

    __half *xh,*lnyh,*ln1h,*atth,*hh;
    __half *wqh,*wkh,*wvh,*woh,*w1h,*w2h;
    cudaGetSymbolAddress((void**)&xh,   g_xh);
    cudaGetSymbolAddress((void**)&lnyh, g_lnyh);
    cudaGetSymbolAddress((void**)&ln1h, g_ln1h);
    cudaGetSymbolAddress((void**)&atth, g_atth);
    cudaGetSymbolAddress((void**)&hh,   g_hh);
    cudaGetSymbolAddress((void**)&wqh,  g_wqh);
    cudaGetSymbolAddress((void**)&wkh,  g_wkh);
    cudaGetSymbolAddress((void**)&wvh,  g_wvh);
    cudaGetSymbolAddress((void**)&woh,  g_woh);
    cudaGetSymbolAddress((void**)&w1h,  g_w1h);
    cudaGetSymbolAddress((void**)&w2h,  g_w2h);

    // operand conversions (independent of LN)
    conv(x,  xh,  BB*LL*DD);
    conv(Wq, wqh, DD*DD);
    conv(Wk, wkh, DD*DD);
    conv(Wv, wvh, DD*DD);
    conv(Wo, woh, DD*DD);
    conv(W1, w1h, DD*DFF);
    conv(W2, w2h, DFF*DD);

    // LN1 on y -> fp16 lny
    ln_reduce1<<<dim3(256, BB), 256>>>(y);
    ln_reduce2<<<BB, 256>>>();
    ln_apply_h<<<dim3(128, BB), 256>>>(y, ln1w, ln1b, lnyh);

    // Q = x@Wq+bq ; K = lny@Wk+bk ; V = lny@Wv+bv  (fp32 outputs)
    tgemm<0,0><<<dim3(DD/128, MM/128), 256>>>(xh,   wqh, bq, nullptr, p_q, nullptr, DD, DD);
    tgemm<0,0><<<dim3(DD/128, MM/128), 256>>>(lnyh, wkh, bk, nullptr, p_k, nullptr, DD, DD);
    tgemm<0,0><<<dim3(DD/128, MM/128), 256>>>(lnyh, wvh, bv, nullptr, p_v, nullptr, DD, DD);

    // suffix sums of V, then attention (writes fp16 attn)
    vsuffix_kernel<<<BB*HH, 1024>>>();
    fattn_kernel<<<dim3(LL/64, HH, BB), 128>>>();

    // y1 = y + attn@Wo + bo  (fp32)
    tgemm<2,0><<<dim3(DD/128, MM/128), 256>>>(atth, woh, bo, y, p_y1, nullptr, DD, DD);

    // LN2 on y1 -> fp16 lny1
    ln_reduce1<<<dim3(256, BB), 256>>>(p_y1);
    ln_reduce2<<<BB, 256>>>();
    ln_apply_h<<<dim3(128, BB), 256>>>(p_y1, ln2w, ln2b, ln1h);

    // h = relu(lny1@W1 + b1) (fp16 out) ; out = y1 + h@W2 + b2 (fp32)
    tgemm<1,1><<<dim3(DFF/128, MM/128), 256>>>(ln1h, w1h, b1, nullptr, nullptr, hh, DFF, DD);
    tgemm<2,0><<<dim3(DD/128,  MM/128), 256>>>(hh,   w2h, b2, p_y1,    out, nullptr, DD, DFF);
}

// round 10
// speedup vs baseline: 2.0635x; 1.1432x over previous
#include <cuda_runtime.h>
#include <cuda_bf16.h>
#include <cuda_fp16.h>
#include <math.h>
#include <stdint.h>

#define BB 2
#define LL 2048
#define DD 1024
#define HH 16
#define DKK 64
#define DFF 4096
#define MM (BB*LL)   // 4096
#define EPS 1e-5f

// ================= helpers =================
__device__ __forceinline__ uint32_t smem_u32(const void* p) {
    uint32_t a;
    asm("{ .reg .u64 t; cvta.to.shared.u64 t, %1; cvt.u32.u64 %0, t; }" : "=r"(a) : "l"(p));
    return a;
}

#define LDSM_X4(r, addr) \
    asm volatile("ldmatrix.sync.aligned.m8n8.x4.shared.b16 {%0,%1,%2,%3}, [%4];" \
        : "=r"((r)[0]), "=r"((r)[1]), "=r"((r)[2]), "=r"((r)[3]) : "r"(addr))
#define LDSM_X4T(r, addr) \
    asm volatile("ldmatrix.sync.aligned.m8n8.x4.trans.shared.b16 {%0,%1,%2,%3}, [%4];" \
        : "=r"((r)[0]), "=r"((r)[1]), "=r"((r)[2]), "=r"((r)[3]) : "r"(addr))

// fp16 mma
#define MMAH16816(d, a, b0, b1) \
    asm volatile("mma.sync.aligned.m16n8k16.row.col.f32.f16.f16.f32 " \
        "{%0,%1,%2,%3}, {%4,%5,%6,%7}, {%8,%9}, {%0,%1,%2,%3};" \
        : "+f"((d)[0]), "+f"((d)[1]), "+f"((d)[2]), "+f"((d)[3]) \
        : "r"((a)[0]), "r"((a)[1]), "r"((a)[2]), "r"((a)[3]), "r"(b0), "r"(b1))

#define STS128U(addr, a, b, c, d) \
    asm volatile("st.shared.v4.b32 [%0], {%1, %2, %3, %4};" \
                 :: "r"((uint32_t)(addr)), "r"(a), "r"(b), "r"(c), "r"(d) : "memory")
#define STS64U(addr, a, b) \
    asm volatile("st.shared.v2.b32 [%0], {%1, %2};" \
                 :: "r"((uint32_t)(addr)), "r"(a), "r"(b) : "memory")

__device__ __forceinline__ uint32_t packh(float x0, float x1) {
    __half2 h = __floats2half2_rn(x0, x1);
    return *reinterpret_cast<uint32_t*>(&h);
}

#define SCQ (0.125f * 1.4426950408889634f)   // 1/sqrt(64) * log2(e)

// ================= scratch =================
__device__ float g_v   [BB*LL*DD];
__device__ float g_vsuf[BB*HH*LL*DKK];
__device__ float g_y1  [BB*LL*DD];
__device__ float g_part[BB*256*2];
__device__ float g_stats[BB*2];

// fp16 operands
__device__ __half g_xh  [BB*LL*DD];
__device__ __half g_lnyh[BB*LL*DD];
__device__ __half g_ln1h[BB*LL*DD];
__device__ __half g_qh  [BB*LL*DD];
__device__ __half g_kh  [BB*LL*DD];
__device__ __half g_atth[BB*LL*DD];
__device__ __half g_hh  [BB*LL*DFF];
__device__ __half g_wqh[DD*DD];
__device__ __half g_wkh[DD*DD];
__device__ __half g_wvh[DD*DD];
__device__ __half g_woh[DD*DD];
__device__ __half g_w1h[DD*DFF];
__device__ __half g_w2h[DFF*DD];

// ================= fp32 -> fp16 convert =================
__global__ void convert_h(const float4* __restrict__ src, uint2* __restrict__ dst, int n4) {
    int i = blockIdx.x * blockDim.x + threadIdx.x;
    if (i < n4) {
        float4 v = src[i];
        dst[i] = make_uint2(packh(v.x, v.y), packh(v.z, v.w));
    }
}

// ================= LayerNorm over (L,D) jointly =================
__global__ void ln_reduce1(const float* __restrict__ x) {
    const int batch = blockIdx.y;
    const int chunk = (LL*DD)/256;
    long base = (long)batch*LL*DD + (long)blockIdx.x*chunk;
    float s = 0.f, s2 = 0.f;
    for (int i = threadIdx.x; i < chunk; i += 256) {
        float v = x[base + i];
        s += v; s2 += v*v;
    }
    __shared__ float sh[256], sh2[256];
    sh[threadIdx.x] = s; sh2[threadIdx.x] = s2;
    __syncthreads();
    for (int o = 128; o > 0; o >>= 1) {
        if (threadIdx.x < o) { sh[threadIdx.x] += sh[threadIdx.x+o]; sh2[threadIdx.x] += sh2[threadIdx.x+o]; }
        __syncthreads();
    }
    if (threadIdx.x == 0) {
        g_part[(batch*256 + blockIdx.x)*2 + 0] = sh[0];
        g_part[(batch*256 + blockIdx.x)*2 + 1] = sh2[0];
    }
}

__global__ void ln_reduce2() {
    const int batch = blockIdx.x;
    __shared__ float sh[256], sh2[256];
    sh[threadIdx.x]  = g_part[(batch*256 + threadIdx.x)*2 + 0];
    sh2[threadIdx.x] = g_part[(batch*256 + threadIdx.x)*2 + 1];
    __syncthreads();
    for (int o = 128; o > 0; o >>= 1) {
        if (threadIdx.x < o) { sh[threadIdx.x] += sh[threadIdx.x+o]; sh2[threadIdx.x] += sh2[threadIdx.x+o]; }
        __syncthreads();
    }
    if (threadIdx.x == 0) {
        const float inv = 1.0f / (float)(LL*DD);
        float mu  = sh[0]  * inv;
        float var = sh2[0] * inv - mu*mu;
        g_stats[batch*2 + 0] = mu;
        g_stats[batch*2 + 1] = rsqrtf(var + EPS);
    }
}

// LN apply writing fp16 directly
__global__ void ln_apply_h(const float* __restrict__ x, const float* __restrict__ w,
                           const float* __restrict__ b, __half* __restrict__ out) {
    const int batch = blockIdx.y;
    const float mu   = g_stats[batch*2 + 0];
    const float rstd = g_stats[batch*2 + 1];
    const long base = (long)batch*LL*DD;
    const int n4 = LL*DD/4;
    for (int i = blockIdx.x*blockDim.x + threadIdx.x; i < n4; i += gridDim.x*blockDim.x) {
        const long idx = (long)i*4;
        float4 xv = *(const float4*)(x + base + idx);
        float4 wv = *(const float4*)(w + idx);
        float4 bv = *(const float4*)(b + idx);
        float v0 = (xv.x - mu)*rstd*wv.x + bv.x;
        float v1 = (xv.y - mu)*rstd*wv.y + bv.y;
        float v2 = (xv.z - mu)*rstd*wv.z + bv.z;
        float v3 = (xv.w - mu)*rstd*wv.w + bv.w;
        *(uint2*)(out + base + idx) = make_uint2(packh(v0, v1), packh(v2, v3));
    }
}

// ================= fp16 single-pass mma.sync GEMM =================
// C[M,N] = A[M,K]@W[K,N] + bias; EPI: 0=bias, 1=bias+relu, 2=bias+residual, 3=(bias)*SCQ
// OUTH: 0 = fp32 out, 1 = fp16 out.
#define ASTR 48
#define OFF_A1 6144
#define OFF_B  12288
#define BSTR 272
#define BSUB 4352
#define STAGE 20992

template<int EPI, int OUTH>
__global__ void __launch_bounds__(256)
tgemm(const __half* __restrict__ A, const __half* __restrict__ W,
      const float* __restrict__ bias, const float* __restrict__ R,
      float* __restrict__ C, __half* __restrict__ Ch, int N, int K)
{
    __shared__ __align__(128) char sm[2*STAGE];
    const uint32_t sbase = smem_u32(sm);

    const int t = threadIdx.x;
    const int lane = t & 31, wid = t >> 5;
    const int g = lane >> 2, tig = lane & 3;
    const int wm = wid >> 2, wn = wid & 3;
    const int bm = blockIdx.y * 128, bn = blockIdx.x * 128;

    const int ar = t >> 1, aq = t & 1;
    const int br = t >> 4, bc = (t & 15) * 8;

    const __half* Agp = A + (size_t)(bm + ar) * K + aq * 8;
    const __half* Bgp = W + (size_t)br * N + bn + bc;

    const uint32_t a_base = sbase + (uint32_t)(wm*64 + (lane & 15)) * ASTR + ((lane >> 4) & 1) * 16;
    const uint32_t b_base = sbase + OFF_B + (uint32_t)(lane & 15) * BSTR + (uint32_t)wn * 64 + ((lane >> 4) & 1) * 16;

    float acc[4][4][4];
    #pragma unroll
    for (int i = 0; i < 4; i++)
        #pragma unroll
        for (int j = 0; j < 4; j++)
            #pragma unroll
            for (int c = 0; c < 4; c++) acc[i][j][c] = 0.f;

    const int nk = K / 32;

    uint4 a0, a1, b0, b1;
    a0 = *(const uint4*)(Agp);
    a1 = *(const uint4*)(Agp + 16);
    b0 = *(const uint4*)(Bgp);
    b1 = *(const uint4*)(Bgp + (size_t)16 * N);

    auto store_stage = [&](int buf) {
        const uint32_t sb = sbase + (uint32_t)buf * STAGE;
        const uint32_t aaddr = sb + (uint32_t)ar * ASTR + (uint32_t)aq * 16;
        STS128U(aaddr,          a0.x, a0.y, a0.z, a0.w);
        STS128U(aaddr + OFF_A1, a1.x, a1.y, a1.z, a1.w);
        const uint32_t baddr = sb + OFF_B + (uint32_t)br * BSTR + (uint32_t)bc * 2;
        STS128U(baddr,        b0.x, b0.y, b0.z, b0.w);
        STS128U(baddr + BSUB, b1.x, b1.y, b1.z, b1.w);
    };

    store_stage(0);
    __syncthreads();

    for (int s = 0; s < nk; s++) {
        const int buf = s & 1;
        if (s + 1 < nk) {
            const int k0 = (s + 1) * 32;
            a0 = *(const uint4*)(Agp + k0);
            a1 = *(const uint4*)(Agp + k0 + 16);
            b0 = *(const uint4*)(Bgp + (size_t)k0 * N);
            b1 = *(const uint4*)(Bgp + (size_t)(k0 + 16) * N);
        }

        const uint32_t so = (uint32_t)buf * STAGE;
        #pragma unroll
        for (int ks = 0; ks < 2; ks++) {
            uint32_t ah[4][4], bf[2][4];
            #pragma unroll
            for (int i = 0; i < 4; i++)
                LDSM_X4(ah[i], a_base + so + ks*OFF_A1 + i*(16*ASTR));
            #pragma unroll
            for (int j2 = 0; j2 < 2; j2++)
                LDSM_X4T(bf[j2], b_base + so + ks*BSUB + j2*32);
            #pragma unroll
            for (int i = 0; i < 4; i++)
                #pragma unroll
                for (int j = 0; j < 4; j++)
                    MMAH16816(acc[i][j], ah[i], bf[j>>1][(j&1)*2], bf[j>>1][(j&1)*2+1]);
        }

        if (s + 1 < nk) store_stage(buf ^ 1);
        __syncthreads();
    }

    // epilogue
    #pragma unroll
    for (int i = 0; i < 4; i++) {
        const int row0 = bm + wm*64 + i*16 + g;
        #pragma unroll
        for (int j = 0; j < 4; j++) {
            const int col0 = bn + wn*32 + j*8 + 2*tig;
            float2 bs = *(const float2*)(bias + col0);
            float2 c01 = make_float2(acc[i][j][0] + bs.x, acc[i][j][1] + bs.y);
            float2 c23 = make_float2(acc[i][j][2] + bs.x, acc[i][j][3] + bs.y);
            if (EPI == 1) {
                c01.x = fmaxf(c01.x, 0.f); c01.y = fmaxf(c01.y, 0.f);
                c23.x = fmaxf(c23.x, 0.f); c23.y = fmaxf(c23.y, 0.f);
            }
            if (EPI == 2) {
                float2 r0 = *(const float2*)(R + (size_t)row0 * N + col0);
                float2 r1 = *(const float2*)(R + (size_t)(row0+8) * N + col0);
                c01.x += r0.x; c01.y += r0.y;
                c23.x += r1.x; c23.y += r1.y;
            }
            if (EPI == 3) {
                c01.x *= SCQ; c01.y *= SCQ; c23.x *= SCQ; c23.y *= SCQ;
            }
            if (OUTH == 0) {
                *(float2*)(C + (size_t)row0 * N + col0)     = c01;
                *(float2*)(C + (size_t)(row0+8) * N + col0) = c23;
            } else {
                *(uint32_t*)(Ch + (size_t)row0 * N + col0)     = packh(c01.x, c01.y);
                *(uint32_t*)(Ch + (size_t)(row0+8) * N + col0) = packh(c23.x, c23.y);
            }
        }
    }
}

// ================= V suffix sums (segmented scan) =================
__global__ void __launch_bounds__(1024) vsuffix_kernel() {
    const int bh = blockIdx.x;
    const int b = bh / HH, h = bh % HH;
    const int d = threadIdx.x & 63;
    const int seg = threadIdx.x >> 6;
    const int SEGK = LL / 16;
    __shared__ float part[16][64];
    const size_t vbase = (size_t)b*LL*DD + (size_t)h*DKK + d;
    const int k0 = seg * SEGK;
    float s = 0.f;
    for (int k = k0; k < k0 + SEGK; k++) s += g_v[vbase + (size_t)k*DD];
    part[seg][d] = s;
    __syncthreads();
    float acc = 0.f;
    for (int ss = seg + 1; ss < 16; ss++) acc += part[ss][d];
    const size_t sb = (size_t)bh*LL*DKK + d;
    for (int k = k0 + SEGK - 1; k >= k0; k--) {
        g_vsuf[sb + (size_t)k*DKK] = acc;
        acc += g_v[vbase + (size_t)k*DD];
    }
}

// ================= fp16 tensor-core flash attention =================
// Q pre-scaled fp16 (g_qh), K fp16 (g_kh), V fp32 -> fp16 in loader.
// 64 q-rows x 64-key chunks, 4 warps; m=0 fixed; tril-to-zero tail via g_vsuf.
#define TSTR 144
#define QTILE 9216

__global__ void __launch_bounds__(128)
fattn_kernel() {
    __shared__ __align__(16) char smr[3*QTILE];
    const uint32_t sQ = smem_u32(smr);
    const uint32_t sK = sQ + QTILE;
    const uint32_t sV = sQ + 2*QTILE;

    const int b = blockIdx.z, h = blockIdx.y;
    const int qt = gridDim.x - 1 - blockIdx.x;   // heavy tiles first
    const int q0 = qt * 64;
    const int t = threadIdx.x, w = t >> 5, lane = t & 31;
    const int g = lane >> 2, tg = lane & 3;
    const int r = t >> 1, hf = t & 1;

    // ---- load Q tile (fp16, already scaled) ----
    {
        const __half* qp = g_qh + ((size_t)(b*LL + q0 + r))*DD + h*DKK + hf*32;
        const uint32_t dq = sQ + (uint32_t)r*TSTR + hf*64;
        uint4 v0 = *(const uint4*)(qp);
        uint4 v1 = *(const uint4*)(qp + 8);
        uint4 v2 = *(const uint4*)(qp + 16);
        uint4 v3 = *(const uint4*)(qp + 24);
        STS128U(dq,      v0.x, v0.y, v0.z, v0.w);
        STS128U(dq + 16, v1.x, v1.y, v1.z, v1.w);
        STS128U(dq + 32, v2.x, v2.y, v2.z, v2.w);
        STS128U(dq + 48, v3.x, v3.y, v3.z, v3.w);
    }
    __syncthreads();

    // ---- preload Q A-fragments (4 k-chunks) ----
    const int mi = lane >> 3, li = lane & 7;
    uint32_t qh[4][4];
    {
        const uint32_t ro = (uint32_t)(w*16 + ((mi&1)<<3) + li) * TSTR + (uint32_t)((mi>>1)<<4);
        #pragma unroll
        for (int kc4 = 0; kc4 < 4; kc4++)
            LDSM_X4(qh[kc4], sQ + ro + kc4*32);
    }

    float oacc[8][4];
    #pragma unroll
    for (int f = 0; f < 8; f++)
        #pragma unroll
        for (int c = 0; c < 4; c++) oacc[f][c] = 0.f;
    float ls0 = 0.f, ls1 = 0.f;

    const int nch = qt + 1;

    for (int ci = 0; ci < nch; ci++) {
        const int kc = ci * 64;
        __syncthreads();
        // ---- load K (fp16 copy) and V (fp32 -> fp16) chunk ----
        {
            const size_t gbase = ((size_t)(b*LL + kc + r))*DD + h*DKK + hf*32;
            const __half* kp = g_kh + gbase;
            const uint32_t dk = sK + (uint32_t)r*TSTR + hf*64;
            uint4 v0 = *(const uint4*)(kp);
            uint4 v1 = *(const uint4*)(kp + 8);
            uint4 v2 = *(const uint4*)(kp + 16);
            uint4 v3 = *(const uint4*)(kp + 24);
            STS128U(dk,      v0.x, v0.y, v0.z, v0.w);
            STS128U(dk + 16, v1.x, v1.y, v1.z, v1.w);
            STS128U(dk + 32, v2.x, v2.y, v2.z, v2.w);
            STS128U(dk + 48, v3.x, v3.y, v3.z, v3.w);
            const float* vp = g_v + gbase;
            const uint32_t dv = sV + (uint32_t)r*TSTR + hf*64;
            #pragma unroll
            for (int j = 0; j < 4; j++) {
                float4 a = *(const float4*)(vp + j*8);
                float4 c = *(const float4*)(vp + j*8 + 4);
                STS128U(dv + j*16, packh(a.x, a.y), packh(a.z, a.w),
                                   packh(c.x, c.y), packh(c.z, c.w));
            }
        }
        __syncthreads();

        // ---- S = Q K^T (single-pass fp16) ----
        float sacc[8][4];
        #pragma unroll
        for (int f = 0; f < 8; f++)
            #pragma unroll
            for (int c = 0; c < 4; c++) sacc[f][c] = 0.f;

        #pragma unroll
        for (int kc4 = 0; kc4 < 4; kc4++) {
            uint32_t bk[8][2];
            #pragma unroll
            for (int j2 = 0; j2 < 4; j2++) {
                uint32_t tmp[4];
                const uint32_t ro = (uint32_t)((2*j2 + (mi>>1))*8 + li) * TSTR
                                  + (uint32_t)(kc4*32 + (mi&1)*16);
                LDSM_X4(tmp, sK + ro);
                bk[2*j2][0] = tmp[0]; bk[2*j2][1] = tmp[1];
                bk[2*j2+1][0] = tmp[2]; bk[2*j2+1][1] = tmp[3];
            }
            #pragma unroll
            for (int f = 0; f < 8; f++) MMAH16816(sacc[f], qh[kc4], bk[f][0], bk[f][1]);
        }

        // ---- P = exp2(S) with causal zero-mask on diagonal chunk ----
        const int row0 = q0 + w*16 + g;
        if (ci == nch - 1) {
            #pragma unroll
            for (int f = 0; f < 8; f++) {
                const int col = kc + f*8 + 2*tg;
                sacc[f][0] = (col   <= row0)   ? exp2f(sacc[f][0]) : 0.f;
                sacc[f][1] = (col+1 <= row0)   ? exp2f(sacc[f][1]) : 0.f;
                sacc[f][2] = (col   <= row0+8) ? exp2f(sacc[f][2]) : 0.f;
                sacc[f][3] = (col+1 <= row0+8) ? exp2f(sacc[f][3]) : 0.f;
            }
        } else {
            #pragma unroll
            for (int f = 0; f < 8; f++) {
                sacc[f][0] = exp2f(sacc[f][0]);
                sacc[f][1] = exp2f(sacc[f][1]);
                sacc[f][2] = exp2f(sacc[f][2]);
                sacc[f][3] = exp2f(sacc[f][3]);
            }
        }
        #pragma unroll
        for (int f = 0; f < 8; f++) {
            ls0 += sacc[f][0] + sacc[f][1];
            ls1 += sacc[f][2] + sacc[f][3];
        }

        // ---- O += P V (fp16) ----
        #pragma unroll
        for (int kc4 = 0; kc4 < 4; kc4++) {
            uint32_t aP[4];
            aP[0] = packh(sacc[2*kc4][0],   sacc[2*kc4][1]);
            aP[1] = packh(sacc[2*kc4][2],   sacc[2*kc4][3]);
            aP[2] = packh(sacc[2*kc4+1][0], sacc[2*kc4+1][1]);
            aP[3] = packh(sacc[2*kc4+1][2], sacc[2*kc4+1][3]);
            uint32_t bv[8][2];
            #pragma unroll
            for (int j2 = 0; j2 < 4; j2++) {
                uint32_t tmp[4];
                const uint32_t ro = (uint32_t)(kc4*16 + (mi&1)*8 + li) * TSTR
                                  + (uint32_t)((2*j2 + (mi>>1))*16);
                LDSM_X4T(tmp, sV + ro);
                bv[2*j2][0] = tmp[0]; bv[2*j2][1] = tmp[1];
                bv[2*j2+1][0] = tmp[2]; bv[2*j2+1][1] = tmp[3];
            }
            #pragma unroll
            for (int f = 0; f < 8; f++) MMAH16816(oacc[f], aP, bv[f][0], bv[f][1]);
        }
    }

    ls0 += __shfl_xor_sync(0xffffffffu, ls0, 1);
    ls0 += __shfl_xor_sync(0xffffffffu, ls0, 2);
    ls1 += __shfl_xor_sync(0xffffffffu, ls1, 1);
    ls1 += __shfl_xor_sync(0xffffffffu, ls1, 2);

    const int row0 = q0 + w*16 + g;
    const int row1 = row0 + 8;
    const float inv0 = 1.0f / (ls0 + (float)(LL - 1 - row0));
    const float inv1 = 1.0f / (ls1 + (float)(LL - 1 - row1));

    const size_t vs0 = ((size_t)((b*HH + h)*LL) + row0) * DKK;
    const size_t vs1 = ((size_t)((b*HH + h)*LL) + row1) * DKK;
    const size_t ob0 = ((size_t)(b*LL + row0))*DD + h*DKK;
    const size_t ob1 = ((size_t)(b*LL + row1))*DD + h*DKK;
    #pragma unroll
    for (int f = 0; f < 8; f++) {
        const int col = f*8 + 2*tg;
        float2 t0 = *(const float2*)(g_vsuf + vs0 + col);
        float2 t1 = *(const float2*)(g_vsuf + vs1 + col);
        *(uint32_t*)(g_atth + ob0 + col) = packh((oacc[f][0] + t0.x) * inv0, (oacc[f][1] + t0.y) * inv0);
        *(uint32_t*)(g_atth + ob1 + col) = packh((oacc[f][2] + t1.x) * inv1, (oacc[f][3] + t1.y) * inv1);
    }
}

// ================= launch =================
static void conv(const float* src, __half* dst, int n) {
    int n4 = n / 4;
    convert_h<<<(n4 + 255)/256, 256>>>((const float4*)src, (uint2*)dst, n4);
}

extern "C" void kernel_launch(void* const* d_in, const int* in_sizes, int n_in,
                              void* d_out, int out_size) {
    const float* x    = (const float*)d_in[0];
    const float* y    = (const float*)d_in[1];
    const float* Wq   = (const float*)d_in[2];
    const float* bq   = (const float*)d_in[3];
    const float* Wk   = (const float*)d_in[4];
    const float* bk   = (const float*)d_in[5];
    const float* Wv   = (const float*)d_in[6];
    const float* bv   = (const float*)d_in[7];
    const float* Wo   = (const float*)d_in[8];
    const float* bo   = (const float*)d_in[9];
    const float* W1   = (const float*)d_in[10];
    const float* b1   = (const float*)d_in[11];
    const float* W2   = (const float*)d_in[12];
    const float* b2   = (const float*)d_in[13];
    const float* ln1w = (const float*)d_in[14];
    const float* ln1b = (const float*)d_in[15];
    const float* ln2w = (const float*)d_in[16];
    const float* ln2b = (const float*)d_in[17];
    float* out = (float*)d_out;

    float *p_v, *p_y1;
    cudaGetSymbolAddress((void**)&p_v,  g_v);
    cudaGetSymbolAddress((void**)&p_y1, g_y1);

    __half *xh,*lnyh,*ln1h,*qh,*kh,*atth,*hh;
    __half *wqh,*wkh,*wvh,*woh,*w1h,*w2h;
    cudaGetSymbolAddress((void**)&xh,   g_xh);
    cudaGetSymbolAddress((void**)&lnyh, g_lnyh);
    cudaGetSymbolAddress((void**)&ln1h, g_ln1h);
    cudaGetSymbolAddress((void**)&qh,   g_qh);
    cudaGetSymbolAddress((void**)&kh,   g_kh);
    cudaGetSymbolAddress((void**)&atth, g_atth);
    cudaGetSymbolAddress((void**)&hh,   g_hh);
    cudaGetSymbolAddress((void**)&wqh,  g_wqh);
    cudaGetSymbolAddress((void**)&wkh,  g_wkh);
    cudaGetSymbolAddress((void**)&wvh,  g_wvh);
    cudaGetSymbolAddress((void**)&woh,  g_woh);
    cudaGetSymbolAddress((void**)&w1h,  g_w1h);
    cudaGetSymbolAddress((void**)&w2h,  g_w2h);

    // operand conversions
    conv(x,  xh,  BB*LL*DD);
    conv(Wq, wqh, DD*DD);
    conv(Wk, wkh, DD*DD);
    conv(Wv, wvh, DD*DD);
    conv(Wo, woh, DD*DD);
    conv(W1, w1h, DD*DFF);
    conv(W2, w2h, DFF*DD);

    // LN1 on y -> fp16 lny
    ln_reduce1<<<dim3(256, BB), 256>>>(y);
    ln_reduce2<<<BB, 256>>>();
    ln_apply_h<<<dim3(128, BB), 256>>>(y, ln1w, ln1b, lnyh);

    // Q (scaled, fp16) ; K (fp16) ; V (fp32)
    tgemm<3,1><<<dim3(DD/128, MM/128), 256>>>(xh,   wqh, bq, nullptr, nullptr, qh, DD, DD);
    tgemm<0,1><<<dim3(DD/128, MM/128), 256>>>(lnyh, wkh, bk, nullptr, nullptr, kh, DD, DD);
    tgemm<0,0><<<dim3(DD/128, MM/128), 256>>>(lnyh, wvh, bv, nullptr, p_v, nullptr, DD, DD);

    // suffix sums of V, then attention (writes fp16 attn)
    vsuffix_kernel<<<BB*HH, 1024>>>();
    fattn_kernel<<<dim3(LL/64, HH, BB), 128>>>();

    // y1 = y + attn@Wo + bo  (fp32)
    tgemm<2,0><<<dim3(DD/128, MM/128), 256>>>(atth, woh, bo, y, p_y1, nullptr, DD, DD);

    // LN2 on y1 -> fp16 lny1
    ln_reduce1<<<dim3(256, BB), 256>>>(p_y1);
    ln_reduce2<<<BB, 256>>>();
    ln_apply_h<<<dim3(128, BB), 256>>>(p_y1, ln2w, ln2b, ln1h);

    // h = relu(lny1@W1 + b1) (fp16 out) ; out = y1 + h@W2 + b2 (fp32)
    tgemm<1,1><<<dim3(DFF/128, MM/128), 256>>>(ln1h, w1h, b1, nullptr, nullptr, hh, DFF, DD);
    tgemm<2,0><<<dim3(DD/128,  MM/128), 256>>>(hh,   w2h, b2, p_y1,    out, nullptr, DD, DFF);
}

// round 11
// speedup vs baseline: 2.2340x; 1.0826x over previous
#include <cuda_runtime.h>
#include <cuda_fp16.h>
#include <math.h>
#include <stdint.h>

#define BB 2
#define LL 2048
#define DD 1024
#define HH 16
#define DKK 64
#define DFF 4096
#define MM (BB*LL)   // 4096
#define EPS 1e-5f

// ================= helpers =================
__device__ __forceinline__ uint32_t smem_u32(const void* p) {
    uint32_t a;
    asm("{ .reg .u64 t; cvta.to.shared.u64 t, %1; cvt.u32.u64 %0, t; }" : "=r"(a) : "l"(p));
    return a;
}

#define LDSM_X4(r, addr) \
    asm volatile("ldmatrix.sync.aligned.m8n8.x4.shared.b16 {%0,%1,%2,%3}, [%4];" \
        : "=r"((r)[0]), "=r"((r)[1]), "=r"((r)[2]), "=r"((r)[3]) : "r"(addr))
#define LDSM_X4T(r, addr) \
    asm volatile("ldmatrix.sync.aligned.m8n8.x4.trans.shared.b16 {%0,%1,%2,%3}, [%4];" \
        : "=r"((r)[0]), "=r"((r)[1]), "=r"((r)[2]), "=r"((r)[3]) : "r"(addr))

// fp16 mma
#define MMAH16816(d, a, b0, b1) \
    asm volatile("mma.sync.aligned.m16n8k16.row.col.f32.f16.f16.f32 " \
        "{%0,%1,%2,%3}, {%4,%5,%6,%7}, {%8,%9}, {%0,%1,%2,%3};" \
        : "+f"((d)[0]), "+f"((d)[1]), "+f"((d)[2]), "+f"((d)[3]) \
        : "r"((a)[0]), "r"((a)[1]), "r"((a)[2]), "r"((a)[3]), "r"(b0), "r"(b1))

#define STS128U(addr, a, b, c, d) \
    asm volatile("st.shared.v4.b32 [%0], {%1, %2, %3, %4};" \
                 :: "r"((uint32_t)(addr)), "r"(a), "r"(b), "r"(c), "r"(d) : "memory")

__device__ __forceinline__ void cpa16(uint32_t dst, const void* src) {
    asm volatile("cp.async.cg.shared.global [%0], [%1], 16;" :: "r"(dst), "l"(src));
}
#define CP_COMMIT() asm volatile("cp.async.commit_group;" ::: "memory")
#define CP_WAIT2()  asm volatile("cp.async.wait_group 2;" ::: "memory")

__device__ __forceinline__ uint32_t packh(float x0, float x1) {
    __half2 h = __floats2half2_rn(x0, x1);
    return *reinterpret_cast<uint32_t*>(&h);
}

#define SCQ (0.125f * 1.4426950408889634f)   // 1/sqrt(64) * log2(e)

// ================= scratch =================
__device__ float g_vsuf[BB*HH*LL*DKK];
__device__ float g_y1  [BB*LL*DD];
__device__ float g_part[BB*256*2];
__device__ float g_stats[BB*2];

// fp16 operands
__device__ __half g_xh  [BB*LL*DD];
__device__ __half g_lnyh[BB*LL*DD];
__device__ __half g_ln1h[BB*LL*DD];
__device__ __half g_qh  [BB*LL*DD];
__device__ __half g_kh  [BB*LL*DD];
__device__ __half g_vh  [BB*LL*DD];
__device__ __half g_atth[BB*LL*DD];
__device__ __half g_hh  [BB*LL*DFF];
__device__ __half g_wqh[DD*DD];
__device__ __half g_wkh[DD*DD];
__device__ __half g_wvh[DD*DD];
__device__ __half g_woh[DD*DD];
__device__ __half g_w1h[DD*DFF];
__device__ __half g_w2h[DFF*DD];

// ================= fp32 -> fp16 convert =================
__global__ void convert_h(const float4* __restrict__ src, uint2* __restrict__ dst, int n4) {
    int i = blockIdx.x * blockDim.x + threadIdx.x;
    if (i < n4) {
        float4 v = src[i];
        dst[i] = make_uint2(packh(v.x, v.y), packh(v.z, v.w));
    }
}

// ================= LayerNorm over (L,D) jointly =================
__global__ void ln_reduce1(const float* __restrict__ x) {
    const int batch = blockIdx.y;
    const int chunk = (LL*DD)/256;
    long base = (long)batch*LL*DD + (long)blockIdx.x*chunk;
    float s = 0.f, s2 = 0.f;
    for (int i = threadIdx.x; i < chunk; i += 256) {
        float v = x[base + i];
        s += v; s2 += v*v;
    }
    __shared__ float sh[256], sh2[256];
    sh[threadIdx.x] = s; sh2[threadIdx.x] = s2;
    __syncthreads();
    for (int o = 128; o > 0; o >>= 1) {
        if (threadIdx.x < o) { sh[threadIdx.x] += sh[threadIdx.x+o]; sh2[threadIdx.x] += sh2[threadIdx.x+o]; }
        __syncthreads();
    }
    if (threadIdx.x == 0) {
        g_part[(batch*256 + blockIdx.x)*2 + 0] = sh[0];
        g_part[(batch*256 + blockIdx.x)*2 + 1] = sh2[0];
    }
}

__global__ void ln_reduce2() {
    const int batch = blockIdx.x;
    __shared__ float sh[256], sh2[256];
    sh[threadIdx.x]  = g_part[(batch*256 + threadIdx.x)*2 + 0];
    sh2[threadIdx.x] = g_part[(batch*256 + threadIdx.x)*2 + 1];
    __syncthreads();
    for (int o = 128; o > 0; o >>= 1) {
        if (threadIdx.x < o) { sh[threadIdx.x] += sh[threadIdx.x+o]; sh2[threadIdx.x] += sh2[threadIdx.x+o]; }
        __syncthreads();
    }
    if (threadIdx.x == 0) {
        const float inv = 1.0f / (float)(LL*DD);
        float mu  = sh[0]  * inv;
        float var = sh2[0] * inv - mu*mu;
        g_stats[batch*2 + 0] = mu;
        g_stats[batch*2 + 1] = rsqrtf(var + EPS);
    }
}

__global__ void ln_apply_h(const float* __restrict__ x, const float* __restrict__ w,
                           const float* __restrict__ b, __half* __restrict__ out) {
    const int batch = blockIdx.y;
    const float mu   = g_stats[batch*2 + 0];
    const float rstd = g_stats[batch*2 + 1];
    const long base = (long)batch*LL*DD;
    const int n4 = LL*DD/4;
    for (int i = blockIdx.x*blockDim.x + threadIdx.x; i < n4; i += gridDim.x*blockDim.x) {
        const long idx = (long)i*4;
        float4 xv = *(const float4*)(x + base + idx);
        float4 wv = *(const float4*)(w + idx);
        float4 bv = *(const float4*)(b + idx);
        float v0 = (xv.x - mu)*rstd*wv.x + bv.x;
        float v1 = (xv.y - mu)*rstd*wv.y + bv.y;
        float v2 = (xv.z - mu)*rstd*wv.z + bv.z;
        float v3 = (xv.w - mu)*rstd*wv.w + bv.w;
        *(uint2*)(out + base + idx) = make_uint2(packh(v0, v1), packh(v2, v3));
    }
}

// ================= fp16 cp.async-pipelined mma.sync GEMM =================
// C[M,N] = A[M,K]@W[K,N] + bias; EPI: 0=bias, 1=bias+relu, 2=bias+residual, 3=(bias)*SCQ
// OUTH: 0 = fp32 out, 1 = fp16 out.
// CTA 256 thr, tile 128x128, k-chunk 32, 4-stage cp.async ring.
#define ASTR 48
#define OFF_A1 6144
#define OFF_B  12288
#define BSTR 272
#define BSUB 4352
#define STAGE 20992
#define SMEM_GEMM4 (4*STAGE)

template<int EPI, int OUTH>
__global__ void __launch_bounds__(256)
tgemm(const __half* __restrict__ A, const __half* __restrict__ W,
      const float* __restrict__ bias, const float* __restrict__ R,
      float* __restrict__ C, __half* __restrict__ Ch, int N, int K)
{
    extern __shared__ __align__(128) char sm[];
    const uint32_t sbase = smem_u32(sm);

    const int t = threadIdx.x;
    const int lane = t & 31, wid = t >> 5;
    const int g = lane >> 2, tig = lane & 3;
    const int wm = wid >> 2, wn = wid & 3;
    const int bm = blockIdx.y * 128, bn = blockIdx.x * 128;

    const int ar = t >> 1, aq = t & 1;
    const int br = t >> 4, bc = (t & 15) * 8;

    const __half* Agp = A + (size_t)(bm + ar) * K + aq * 8;
    const __half* Bgp = W + (size_t)br * N + bn + bc;

    const uint32_t a_sts = (uint32_t)ar * ASTR + (uint32_t)aq * 16;
    const uint32_t b_sts = (uint32_t)br * BSTR + (uint32_t)bc * 2;

    const uint32_t a_base = sbase + (uint32_t)(wm*64 + (lane & 15)) * ASTR + ((lane >> 4) & 1) * 16;
    const uint32_t b_base = sbase + OFF_B + (uint32_t)(lane & 15) * BSTR + (uint32_t)wn * 64 + ((lane >> 4) & 1) * 16;

    float acc[4][4][4];
    #pragma unroll
    for (int i = 0; i < 4; i++)
        #pragma unroll
        for (int j = 0; j < 4; j++)
            #pragma unroll
            for (int c = 0; c < 4; c++) acc[i][j][c] = 0.f;

    const int nk = K / 32;

    auto issue = [&](int s) {
        const uint32_t sb = sbase + (uint32_t)(s & 3) * STAGE;
        const int k0 = s * 32;
        cpa16(sb + a_sts,          Agp + k0);
        cpa16(sb + OFF_A1 + a_sts, Agp + k0 + 16);
        cpa16(sb + OFF_B + b_sts,        Bgp + (size_t)k0 * N);
        cpa16(sb + OFF_B + b_sts + BSUB, Bgp + (size_t)(k0 + 16) * N);
    };

    issue(0); CP_COMMIT();
    if (nk > 1) issue(1);
    CP_COMMIT();
    if (nk > 2) issue(2);
    CP_COMMIT();

    for (int s = 0; s < nk; s++) {
        CP_WAIT2();
        __syncthreads();
        if (s + 3 < nk) issue(s + 3);
        CP_COMMIT();

        const uint32_t so = (uint32_t)(s & 3) * STAGE;
        #pragma unroll
        for (int ks = 0; ks < 2; ks++) {
            uint32_t ah[4][4], bf[2][4];
            #pragma unroll
            for (int i = 0; i < 4; i++)
                LDSM_X4(ah[i], a_base + so + ks*OFF_A1 + i*(16*ASTR));
            #pragma unroll
            for (int j2 = 0; j2 < 2; j2++)
                LDSM_X4T(bf[j2], b_base + so + ks*BSUB + j2*32);
            #pragma unroll
            for (int i = 0; i < 4; i++)
                #pragma unroll
                for (int j = 0; j < 4; j++)
                    MMAH16816(acc[i][j], ah[i], bf[j>>1][(j&1)*2], bf[j>>1][(j&1)*2+1]);
        }
    }

    // epilogue
    #pragma unroll
    for (int i = 0; i < 4; i++) {
        const int row0 = bm + wm*64 + i*16 + g;
        #pragma unroll
        for (int j = 0; j < 4; j++) {
            const int col0 = bn + wn*32 + j*8 + 2*tig;
            float2 bs = *(const float2*)(bias + col0);
            float2 c01 = make_float2(acc[i][j][0] + bs.x, acc[i][j][1] + bs.y);
            float2 c23 = make_float2(acc[i][j][2] + bs.x, acc[i][j][3] + bs.y);
            if (EPI == 1) {
                c01.x = fmaxf(c01.x, 0.f); c01.y = fmaxf(c01.y, 0.f);
                c23.x = fmaxf(c23.x, 0.f); c23.y = fmaxf(c23.y, 0.f);
            }
            if (EPI == 2) {
                float2 r0 = *(const float2*)(R + (size_t)row0 * N + col0);
                float2 r1 = *(const float2*)(R + (size_t)(row0+8) * N + col0);
                c01.x += r0.x; c01.y += r0.y;
                c23.x += r1.x; c23.y += r1.y;
            }
            if (EPI == 3) {
                c01.x *= SCQ; c01.y *= SCQ; c23.x *= SCQ; c23.y *= SCQ;
            }
            if (OUTH == 0) {
                *(float2*)(C + (size_t)row0 * N + col0)     = c01;
                *(float2*)(C + (size_t)(row0+8) * N + col0) = c23;
            } else {
                *(uint32_t*)(Ch + (size_t)row0 * N + col0)     = packh(c01.x, c01.y);
                *(uint32_t*)(Ch + (size_t)(row0+8) * N + col0) = packh(c23.x, c23.y);
            }
        }
    }
}

// ================= V suffix sums (fp16 V, segmented scan) =================
__global__ void __launch_bounds__(1024) vsuffix_kernel() {
    const int bh = blockIdx.x;
    const int b = bh / HH, h = bh % HH;
    const int d = threadIdx.x & 63;
    const int seg = threadIdx.x >> 6;
    const int SEGK = LL / 16;
    __shared__ float part[16][64];
    const size_t vbase = (size_t)b*LL*DD + (size_t)h*DKK + d;
    const int k0 = seg * SEGK;
    float s = 0.f;
    for (int k = k0; k < k0 + SEGK; k++) s += __half2float(g_vh[vbase + (size_t)k*DD]);
    part[seg][d] = s;
    __syncthreads();
    float acc = 0.f;
    for (int ss = seg + 1; ss < 16; ss++) acc += part[ss][d];
    const size_t sb = (size_t)bh*LL*DKK + d;
    for (int k = k0 + SEGK - 1; k >= k0; k--) {
        g_vsuf[sb + (size_t)k*DKK] = acc;
        acc += __half2float(g_vh[vbase + (size_t)k*DD]);
    }
}

// ================= fp16 tensor-core flash attention =================
#define TSTR 144
#define QTILE 9216

__global__ void __launch_bounds__(128)
fattn_kernel() {
    __shared__ __align__(16) char smr[3*QTILE];
    const uint32_t sQ = smem_u32(smr);
    const uint32_t sK = sQ + QTILE;
    const uint32_t sV = sQ + 2*QTILE;

    const int b = blockIdx.z, h = blockIdx.y;
    const int qt = gridDim.x - 1 - blockIdx.x;   // heavy tiles first
    const int q0 = qt * 64;
    const int t = threadIdx.x, w = t >> 5, lane = t & 31;
    const int g = lane >> 2, tg = lane & 3;
    const int r = t >> 1, hf = t & 1;

    // ---- load Q tile (fp16, already scaled) ----
    {
        const __half* qp = g_qh + ((size_t)(b*LL + q0 + r))*DD + h*DKK + hf*32;
        const uint32_t dq = sQ + (uint32_t)r*TSTR + hf*64;
        uint4 v0 = *(const uint4*)(qp);
        uint4 v1 = *(const uint4*)(qp + 8);
        uint4 v2 = *(const uint4*)(qp + 16);
        uint4 v3 = *(const uint4*)(qp + 24);
        STS128U(dq,      v0.x, v0.y, v0.z, v0.w);
        STS128U(dq + 16, v1.x, v1.y, v1.z, v1.w);
        STS128U(dq + 32, v2.x, v2.y, v2.z, v2.w);
        STS128U(dq + 48, v3.x, v3.y, v3.z, v3.w);
    }
    __syncthreads();

    const int mi = lane >> 3, li = lane & 7;
    uint32_t qh[4][4];
    {
        const uint32_t ro = (uint32_t)(w*16 + ((mi&1)<<3) + li) * TSTR + (uint32_t)((mi>>1)<<4);
        #pragma unroll
        for (int kc4 = 0; kc4 < 4; kc4++)
            LDSM_X4(qh[kc4], sQ + ro + kc4*32);
    }

    float oacc[8][4];
    #pragma unroll
    for (int f = 0; f < 8; f++)
        #pragma unroll
        for (int c = 0; c < 4; c++) oacc[f][c] = 0.f;
    float ls0 = 0.f, ls1 = 0.f;

    const int nch = qt + 1;

    for (int ci = 0; ci < nch; ci++) {
        const int kc = ci * 64;
        __syncthreads();
        // ---- load K and V chunks (raw fp16 copies) ----
        {
            const size_t gbase = ((size_t)(b*LL + kc + r))*DD + h*DKK + hf*32;
            const __half* kp = g_kh + gbase;
            const uint32_t dk = sK + (uint32_t)r*TSTR + hf*64;
            uint4 v0 = *(const uint4*)(kp);
            uint4 v1 = *(const uint4*)(kp + 8);
            uint4 v2 = *(const uint4*)(kp + 16);
            uint4 v3 = *(const uint4*)(kp + 24);
            STS128U(dk,      v0.x, v0.y, v0.z, v0.w);
            STS128U(dk + 16, v1.x, v1.y, v1.z, v1.w);
            STS128U(dk + 32, v2.x, v2.y, v2.z, v2.w);
            STS128U(dk + 48, v3.x, v3.y, v3.z, v3.w);
            const __half* vp = g_vh + gbase;
            const uint32_t dv = sV + (uint32_t)r*TSTR + hf*64;
            v0 = *(const uint4*)(vp);
            v1 = *(const uint4*)(vp + 8);
            v2 = *(const uint4*)(vp + 16);
            v3 = *(const uint4*)(vp + 24);
            STS128U(dv,      v0.x, v0.y, v0.z, v0.w);
            STS128U(dv + 16, v1.x, v1.y, v1.z, v1.w);
            STS128U(dv + 32, v2.x, v2.y, v2.z, v2.w);
            STS128U(dv + 48, v3.x, v3.y, v3.z, v3.w);
        }
        __syncthreads();

        // ---- S = Q K^T (fp16) ----
        float sacc[8][4];
        #pragma unroll
        for (int f = 0; f < 8; f++)
            #pragma unroll
            for (int c = 0; c < 4; c++) sacc[f][c] = 0.f;

        #pragma unroll
        for (int kc4 = 0; kc4 < 4; kc4++) {
            uint32_t bk[8][2];
            #pragma unroll
            for (int j2 = 0; j2 < 4; j2++) {
                uint32_t tmp[4];
                const uint32_t ro = (uint32_t)((2*j2 + (mi>>1))*8 + li) * TSTR
                                  + (uint32_t)(kc4*32 + (mi&1)*16);
                LDSM_X4(tmp, sK + ro);
                bk[2*j2][0] = tmp[0]; bk[2*j2][1] = tmp[1];
                bk[2*j2+1][0] = tmp[2]; bk[2*j2+1][1] = tmp[3];
            }
            #pragma unroll
            for (int f = 0; f < 8; f++) MMAH16816(sacc[f], qh[kc4], bk[f][0], bk[f][1]);
        }

        // ---- P = exp2(S) with causal zero-mask on diagonal chunk ----
        const int row0 = q0 + w*16 + g;
        if (ci == nch - 1) {
            #pragma unroll
            for (int f = 0; f < 8; f++) {
                const int col = kc + f*8 + 2*tg;
                sacc[f][0] = (col   <= row0)   ? exp2f(sacc[f][0]) : 0.f;
                sacc[f][1] = (col+1 <= row0)   ? exp2f(sacc[f][1]) : 0.f;
                sacc[f][2] = (col   <= row0+8) ? exp2f(sacc[f][2]) : 0.f;
                sacc[f][3] = (col+1 <= row0+8) ? exp2f(sacc[f][3]) : 0.f;
            }
        } else {
            #pragma unroll
            for (int f = 0; f < 8; f++) {
                sacc[f][0] = exp2f(sacc[f][0]);
                sacc[f][1] = exp2f(sacc[f][1]);
                sacc[f][2] = exp2f(sacc[f][2]);
                sacc[f][3] = exp2f(sacc[f][3]);
            }
        }
        #pragma unroll
        for (int f = 0; f < 8; f++) {
            ls0 += sacc[f][0] + sacc[f][1];
            ls1 += sacc[f][2] + sacc[f][3];
        }

        // ---- O += P V (fp16) ----
        #pragma unroll
        for (int kc4 = 0; kc4 < 4; kc4++) {
            uint32_t aP[4];
            aP[0] = packh(sacc[2*kc4][0],   sacc[2*kc4][1]);
            aP[1] = packh(sacc[2*kc4][2],   sacc[2*kc4][3]);
            aP[2] = packh(sacc[2*kc4+1][0], sacc[2*kc4+1][1]);
            aP[3] = packh(sacc[2*kc4+1][2], sacc[2*kc4+1][3]);
            uint32_t bv[8][2];
            #pragma unroll
            for (int j2 = 0; j2 < 4; j2++) {
                uint32_t tmp[4];
                const uint32_t ro = (uint32_t)(kc4*16 + (mi&1)*8 + li) * TSTR
                                  + (uint32_t)((2*j2 + (mi>>1))*16);
                LDSM_X4T(tmp, sV + ro);
                bv[2*j2][0] = tmp[0]; bv[2*j2][1] = tmp[1];
                bv[2*j2+1][0] = tmp[2]; bv[2*j2+1][1] = tmp[3];
            }
            #pragma unroll
            for (int f = 0; f < 8; f++) MMAH16816(oacc[f], aP, bv[f][0], bv[f][1]);
        }
    }

    ls0 += __shfl_xor_sync(0xffffffffu, ls0, 1);
    ls0 += __shfl_xor_sync(0xffffffffu, ls0, 2);
    ls1 += __shfl_xor_sync(0xffffffffu, ls1, 1);
    ls1 += __shfl_xor_sync(0xffffffffu, ls1, 2);

    const int row0 = q0 + w*16 + g;
    const int row1 = row0 + 8;
    const float inv0 = 1.0f / (ls0 + (float)(LL - 1 - row0));
    const float inv1 = 1.0f / (ls1 + (float)(LL - 1 - row1));

    const size_t vs0 = ((size_t)((b*HH + h)*LL) + row0) * DKK;
    const size_t vs1 = ((size_t)((b*HH + h)*LL) + row1) * DKK;
    const size_t ob0 = ((size_t)(b*LL + row0))*DD + h*DKK;
    const size_t ob1 = ((size_t)(b*LL + row1))*DD + h*DKK;
    #pragma unroll
    for (int f = 0; f < 8; f++) {
        const int col = f*8 + 2*tg;
        float2 t0 = *(const float2*)(g_vsuf + vs0 + col);
        float2 t1 = *(const float2*)(g_vsuf + vs1 + col);
        *(uint32_t*)(g_atth + ob0 + col) = packh((oacc[f][0] + t0.x) * inv0, (oacc[f][1] + t0.y) * inv0);
        *(uint32_t*)(g_atth + ob1 + col) = packh((oacc[f][2] + t1.x) * inv1, (oacc[f][3] + t1.y) * inv1);
    }
}

// ================= launch =================
static void conv(const float* src, __half* dst, int n) {
    int n4 = n / 4;
    convert_h<<<(n4 + 255)/256, 256>>>((const float4*)src, (uint2*)dst, n4);
}

extern "C" void kernel_launch(void* const* d_in, const int* in_sizes, int n_in,
                              void* d_out, int out_size) {
    const float* x    = (const float*)d_in[0];
    const float* y    = (const float*)d_in[1];
    const float* Wq   = (const float*)d_in[2];
    const float* bq   = (const float*)d_in[3];
    const float* Wk   = (const float*)d_in[4];
    const float* bk   = (const float*)d_in[5];
    const float* Wv   = (const float*)d_in[6];
    const float* bv   = (const float*)d_in[7];
    const float* Wo   = (const float*)d_in[8];
    const float* bo   = (const float*)d_in[9];
    const float* W1   = (const float*)d_in[10];
    const float* b1   = (const float*)d_in[11];
    const float* W2   = (const float*)d_in[12];
    const float* b2   = (const float*)d_in[13];
    const float* ln1w = (const float*)d_in[14];
    const float* ln1b = (const float*)d_in[15];
    const float* ln2w = (const float*)d_in[16];
    const float* ln2b = (const float*)d_in[17];
    float* out = (float*)d_out;

    float *p_y1;
    cudaGetSymbolAddress((void**)&p_y1, g_y1);

    __half *xh,*lnyh,*ln1h,*qh,*kh,*vh,*atth,*hh;
    __half *wqh,*wkh,*wvh,*woh,*w1h,*w2h;
    cudaGetSymbolAddress((void**)&xh,   g_xh);
    cudaGetSymbolAddress((void**)&lnyh, g_lnyh);
    cudaGetSymbolAddress((void**)&ln1h, g_ln1h);
    cudaGetSymbolAddress((void**)&qh,   g_qh);
    cudaGetSymbolAddress((void**)&kh,   g_kh);
    cudaGetSymbolAddress((void**)&vh,   g_vh);
    cudaGetSymbolAddress((void**)&atth, g_atth);
    cudaGetSymbolAddress((void**)&hh,   g_hh);
    cudaGetSymbolAddress((void**)&wqh,  g_wqh);
    cudaGetSymbolAddress((void**)&wkh,  g_wkh);
    cudaGetSymbolAddress((void**)&wvh,  g_wvh);
    cudaGetSymbolAddress((void**)&woh,  g_woh);
    cudaGetSymbolAddress((void**)&w1h,  g_w1h);
    cudaGetSymbolAddress((void**)&w2h,  g_w2h);

    cudaFuncSetAttribute(tgemm<3,1>, cudaFuncAttributeMaxDynamicSharedMemorySize, SMEM_GEMM4);
    cudaFuncSetAttribute(tgemm<0,1>, cudaFuncAttributeMaxDynamicSharedMemorySize, SMEM_GEMM4);
    cudaFuncSetAttribute(tgemm<2,0>, cudaFuncAttributeMaxDynamicSharedMemorySize, SMEM_GEMM4);
    cudaFuncSetAttribute(tgemm<1,1>, cudaFuncAttributeMaxDynamicSharedMemorySize, SMEM_GEMM4);

    // operand conversions
    conv(x,  xh,  BB*LL*DD);
    conv(Wq, wqh, DD*DD);
    conv(Wk, wkh, DD*DD);
    conv(Wv, wvh, DD*DD);
    conv(Wo, woh, DD*DD);
    conv(W1, w1h, DD*DFF);
    conv(W2, w2h, DFF*DD);

    // LN1 on y -> fp16 lny
    ln_reduce1<<<dim3(256, BB), 256>>>(y);
    ln_reduce2<<<BB, 256>>>();
    ln_apply_h<<<dim3(128, BB), 256>>>(y, ln1w, ln1b, lnyh);

    // Q (scaled, fp16) ; K (fp16) ; V (fp16)
    tgemm<3,1><<<dim3(DD/128, MM/128), 256, SMEM_GEMM4>>>(xh,   wqh, bq, nullptr, nullptr, qh, DD, DD);
    tgemm<0,1><<<dim3(DD/128, MM/128), 256, SMEM_GEMM4>>>(lnyh, wkh, bk, nullptr, nullptr, kh, DD, DD);
    tgemm<0,1><<<dim3(DD/128, MM/128), 256, SMEM_GEMM4>>>(lnyh, wvh, bv, nullptr, nullptr, vh, DD, DD);

    // suffix sums of V, then attention (writes fp16 attn)
    vsuffix_kernel<<<BB*HH, 1024>>>();
    fattn_kernel<<<dim3(LL/64, HH, BB), 128>>>();

    // y1 = y + attn@Wo + bo  (fp32)
    tgemm<2,0><<<dim3(DD/128, MM/128), 256, SMEM_GEMM4>>>(atth, woh, bo, y, p_y1, nullptr, DD, DD);

    // LN2 on y1 -> fp16 lny1
    ln_reduce1<<<dim3(256, BB), 256>>>(p_y1);
    ln_reduce2<<<BB, 256>>>();
    ln_apply_h<<<dim3(128, BB), 256>>>(p_y1, ln2w, ln2b, ln1h);

    // h = relu(lny1@W1 + b1) (fp16 out) ; out = y1 + h@W2 + b2 (fp32)
    tgemm<1,1><<<dim3(DFF/128, MM/128), 256, SMEM_GEMM4>>>(ln1h, w1h, b1, nullptr, nullptr, hh, DFF, DD);
    tgemm<2,0><<<dim3(DD/128,  MM/128), 256, SMEM_GEMM4>>>(hh,   w2h, b2, p_y1,    out, nullptr, DD, DFF);
}